// round 3
// baseline (speedup 1.0000x reference)
#include <cuda_runtime.h>
#include <math.h>

#define B_ 4
#define S_ 2048
#define E_ 1024
#define H_ 16
#define D_ 64
#define NTOK (B_*S_)   // 8192

// ---------------- scratch (__device__ globals: sanctioned, no allocs) ----------------
__device__ float d_Q[(size_t)NTOK*E_];
__device__ float d_K[(size_t)NTOK*E_];
__device__ float d_V[(size_t)NTOK*E_];
__device__ float d_AO[(size_t)NTOK*E_];
__device__ float d_P[(size_t)B_*H_*S_*S_];   // 268,435,456 floats = 1.07 GB
__device__ float d_ct[S_*32];
__device__ float d_st[S_*32];

// ---------------- exp without MUFU, transform-proof (no magic-number trick) ----------------
// e^x = 2^n * e^(f*ln2),  n = rint(x*log2e), f = x*log2e - n in [-0.5, 0.5]
__device__ __forceinline__ float fast_exp(float x) {
    float t  = x * 1.44269504088896341f;
    t = fmaxf(fminf(t, 126.0f), -126.0f);
    float fn = rintf(t);                 // FRND: exact, cannot be folded away
    int   n  = (int)fn;                  // exact F2I
    float f  = t - fn;                   // [-0.5, 0.5]
    float g  = f * 0.69314718055994531f; // [-0.347, 0.347]
    float p  = 1.0f + g*(1.0f + g*(0.5f + g*(0.16666666667f + g*(0.04166666667f + g*0.008333333333f))));
    return __int_as_float((n + 127) << 23) * p;
}

// ---------------- NT SGEMM: C[M,N] = scale * A[M,K] * B[N,K]^T (+ bias[N]) ----------------
// 128x128 block tile, BK=16, 256 threads, 8x8 microtile.
// MODE 0: plain. MODE 1: batched per (b,h) attention scores with head offsets.
template<int MODE>
__global__ void __launch_bounds__(256, 2) sgemm_nt(
    const float* __restrict__ A, const float* __restrict__ B,
    const float* __restrict__ bias, float* __restrict__ C,
    int K, int lda, int ldb, int ldc, float scale)
{
    __shared__ float As[16][128];
    __shared__ float Bs[16][128];

    const float* Ap = A;
    const float* Bp = B;
    float* Cp = C;
    if (MODE == 1) {
        int z = blockIdx.z;
        int b = z >> 4, h = z & 15;
        size_t off = (size_t)b * S_ * E_ + (size_t)h * D_;
        Ap += off; Bp += off;
        Cp += (size_t)z * S_ * S_;
    }

    int t  = threadIdx.x;
    int lr = t >> 2;            // 0..63
    int lc = (t & 3) << 2;      // 0,4,8,12
    int ty = t >> 4, tx = t & 15;
    size_t brow = (size_t)blockIdx.y * 128;
    size_t bcol = (size_t)blockIdx.x * 128;

    float acc[8][8];
    #pragma unroll
    for (int i = 0; i < 8; i++)
        #pragma unroll
        for (int j = 0; j < 8; j++) acc[i][j] = 0.0f;

    for (int k0 = 0; k0 < K; k0 += 16) {
        float4 a0 = *(const float4*)(Ap + (brow + lr)      * (size_t)lda + k0 + lc);
        float4 a1 = *(const float4*)(Ap + (brow + lr + 64) * (size_t)lda + k0 + lc);
        float4 b0 = *(const float4*)(Bp + (bcol + lr)      * (size_t)ldb + k0 + lc);
        float4 b1 = *(const float4*)(Bp + (bcol + lr + 64) * (size_t)ldb + k0 + lc);
        __syncthreads();
        As[lc+0][lr]    = a0.x; As[lc+1][lr]    = a0.y; As[lc+2][lr]    = a0.z; As[lc+3][lr]    = a0.w;
        As[lc+0][lr+64] = a1.x; As[lc+1][lr+64] = a1.y; As[lc+2][lr+64] = a1.z; As[lc+3][lr+64] = a1.w;
        Bs[lc+0][lr]    = b0.x; Bs[lc+1][lr]    = b0.y; Bs[lc+2][lr]    = b0.z; Bs[lc+3][lr]    = b0.w;
        Bs[lc+0][lr+64] = b1.x; Bs[lc+1][lr+64] = b1.y; Bs[lc+2][lr+64] = b1.z; Bs[lc+3][lr+64] = b1.w;
        __syncthreads();
        #pragma unroll
        for (int kk = 0; kk < 16; kk++) {
            float4 af0 = *(const float4*)&As[kk][ty*8];
            float4 af1 = *(const float4*)&As[kk][ty*8+4];
            float4 bf0 = *(const float4*)&Bs[kk][tx*8];
            float4 bf1 = *(const float4*)&Bs[kk][tx*8+4];
            float a[8] = {af0.x,af0.y,af0.z,af0.w,af1.x,af1.y,af1.z,af1.w};
            float b[8] = {bf0.x,bf0.y,bf0.z,bf0.w,bf1.x,bf1.y,bf1.z,bf1.w};
            #pragma unroll
            for (int i = 0; i < 8; i++)
                #pragma unroll
                for (int j = 0; j < 8; j++)
                    acc[i][j] = fmaf(a[i], b[j], acc[i][j]);
        }
    }

    #pragma unroll
    for (int i = 0; i < 8; i++) {
        size_t row = brow + ty*8 + i;
        float* crow = Cp + row * (size_t)ldc + bcol + tx*8;
        #pragma unroll
        for (int j = 0; j < 8; j += 4) {
            float4 v;
            v.x = acc[i][j+0]*scale; v.y = acc[i][j+1]*scale;
            v.z = acc[i][j+2]*scale; v.w = acc[i][j+3]*scale;
            if (bias) {
                size_t col = bcol + tx*8 + j;
                v.x += bias[col]; v.y += bias[col+1]; v.z += bias[col+2]; v.w += bias[col+3];
            }
            *(float4*)(crow + j) = v;
        }
    }
}

// ---------------- RoPE cos/sin table (double precision, one-time) ----------------
__global__ void build_rope_table(float* __restrict__ ct, float* __restrict__ st) {
    int idx = blockIdx.x * blockDim.x + threadIdx.x;
    if (idx >= S_ * 32) return;
    int i = idx & 31;
    int s = idx >> 5;
    double expo = ((double)(2*i)) / 64.0;
    double invf = pow(10000.0, -expo);
    double f = (double)s * invf;
    ct[idx] = (float)cos(f);
    st[idx] = (float)sin(f);
}

// ---------------- RoPE apply (in place, Q then K) ----------------
__global__ void rope_apply(float* __restrict__ Q, float* __restrict__ K,
                           const float* __restrict__ ct, const float* __restrict__ st) {
    int id = blockIdx.x * blockDim.x + threadIdx.x;
    const int total = NTOK * H_ * 32;            // 4,194,304
    if (id >= 2 * total) return;
    float* X = (id < total) ? Q : K;
    int r = (id < total) ? id : id - total;
    int i    = r & 31;
    int h    = (r >> 5) & 15;
    int trow = r >> 9;                           // 0..8191
    int s    = trow & (S_ - 1);
    float c  = ct[s*32 + i];
    float sn = st[s*32 + i];
    float* p = X + (size_t)trow * E_ + h * D_ + i;
    float x1 = p[0], x2 = p[32];
    p[0]  = x1 * c - x2 * sn;
    p[32] = x2 * c + x1 * sn;
}

// ---------------- Row softmax over P (one block per 2048-wide row) ----------------
__global__ void __launch_bounds__(256) softmax_rows(float* __restrict__ P) {
    __shared__ float red[8];
    size_t row = blockIdx.x;
    float* p = P + row * (size_t)S_;
    int t = threadIdx.x;
    float4 v0 = ((float4*)p)[t];
    float4 v1 = ((float4*)p)[t + 256];

    float m = fmaxf(fmaxf(fmaxf(v0.x, v0.y), fmaxf(v0.z, v0.w)),
                    fmaxf(fmaxf(v1.x, v1.y), fmaxf(v1.z, v1.w)));
    #pragma unroll
    for (int o = 16; o; o >>= 1) m = fmaxf(m, __shfl_xor_sync(0xffffffffu, m, o));
    int warp = t >> 5, lane = t & 31;
    if (lane == 0) red[warp] = m;
    __syncthreads();
    if (t == 0) {
        float mm = red[0];
        #pragma unroll
        for (int w = 1; w < 8; w++) mm = fmaxf(mm, red[w]);
        red[0] = mm;
    }
    __syncthreads();
    m = red[0];
    __syncthreads();

    v0.x = fast_exp(v0.x - m); v0.y = fast_exp(v0.y - m);
    v0.z = fast_exp(v0.z - m); v0.w = fast_exp(v0.w - m);
    v1.x = fast_exp(v1.x - m); v1.y = fast_exp(v1.y - m);
    v1.z = fast_exp(v1.z - m); v1.w = fast_exp(v1.w - m);

    float s = v0.x + v0.y + v0.z + v0.w + v1.x + v1.y + v1.z + v1.w;
    #pragma unroll
    for (int o = 16; o; o >>= 1) s += __shfl_xor_sync(0xffffffffu, s, o);
    if (lane == 0) red[warp] = s;
    __syncthreads();
    if (t == 0) {
        float ss = red[0];
        #pragma unroll
        for (int w = 1; w < 8; w++) ss += red[w];
        red[0] = 1.0f / ss;                       // one rcp per row
    }
    __syncthreads();
    float inv = red[0];

    v0.x *= inv; v0.y *= inv; v0.z *= inv; v0.w *= inv;
    v1.x *= inv; v1.y *= inv; v1.z *= inv; v1.w *= inv;
    ((float4*)p)[t]       = v0;
    ((float4*)p)[t + 256] = v1;
}

// ---------------- O = P * V per (b,h): M=2048, N=64, K=2048 ----------------
__global__ void __launch_bounds__(128) pv_gemm(const float* __restrict__ P,
                                               const float* __restrict__ V,
                                               float* __restrict__ AO)
{
    __shared__ float Ps[16][128];
    __shared__ float Vs[16][64];
    int z = blockIdx.z;
    int b = z >> 4, h = z & 15;
    const float* Pp = P + (size_t)z * S_ * S_;
    const float* Vp = V + (size_t)b * S_ * E_ + h * D_;
    float* Cp = AO + (size_t)b * S_ * E_ + h * D_;
    size_t brow = (size_t)blockIdx.x * 128;
    int t = threadIdx.x;
    int ty = t >> 3, tx = t & 7;

    float acc[8][8];
    #pragma unroll
    for (int i = 0; i < 8; i++)
        #pragma unroll
        for (int j = 0; j < 8; j++) acc[i][j] = 0.0f;

    int k_a = t >> 4;            // 0..7
    int c_a = (t & 15) << 2;     // 0..60

    for (int k0 = 0; k0 < S_; k0 += 16) {
        const float* prow = Pp + (brow + t) * (size_t)S_ + k0;
        float4 p0 = ((const float4*)prow)[0];
        float4 p1 = ((const float4*)prow)[1];
        float4 p2 = ((const float4*)prow)[2];
        float4 p3 = ((const float4*)prow)[3];
        float4 w0 = *(const float4*)(Vp + (size_t)(k0 + k_a)     * E_ + c_a);
        float4 w1 = *(const float4*)(Vp + (size_t)(k0 + k_a + 8) * E_ + c_a);
        __syncthreads();
        Ps[ 0][t] = p0.x; Ps[ 1][t] = p0.y; Ps[ 2][t] = p0.z; Ps[ 3][t] = p0.w;
        Ps[ 4][t] = p1.x; Ps[ 5][t] = p1.y; Ps[ 6][t] = p1.z; Ps[ 7][t] = p1.w;
        Ps[ 8][t] = p2.x; Ps[ 9][t] = p2.y; Ps[10][t] = p2.z; Ps[11][t] = p2.w;
        Ps[12][t] = p3.x; Ps[13][t] = p3.y; Ps[14][t] = p3.z; Ps[15][t] = p3.w;
        *(float4*)&Vs[k_a][c_a]     = w0;
        *(float4*)&Vs[k_a + 8][c_a] = w1;
        __syncthreads();
        #pragma unroll
        for (int kk = 0; kk < 16; kk++) {
            float4 af0 = *(const float4*)&Ps[kk][ty*8];
            float4 af1 = *(const float4*)&Ps[kk][ty*8+4];
            float4 bf0 = *(const float4*)&Vs[kk][tx*8];
            float4 bf1 = *(const float4*)&Vs[kk][tx*8+4];
            float a[8] = {af0.x,af0.y,af0.z,af0.w,af1.x,af1.y,af1.z,af1.w};
            float bb[8] = {bf0.x,bf0.y,bf0.z,bf0.w,bf1.x,bf1.y,bf1.z,bf1.w};
            #pragma unroll
            for (int i = 0; i < 8; i++)
                #pragma unroll
                for (int j = 0; j < 8; j++)
                    acc[i][j] = fmaf(a[i], bb[j], acc[i][j]);
        }
    }

    #pragma unroll
    for (int i = 0; i < 8; i++) {
        size_t row = brow + ty*8 + i;
        float* crow = Cp + row * (size_t)E_ + tx*8;
        #pragma unroll
        for (int j = 0; j < 8; j += 4) {
            float4 v;
            v.x = acc[i][j+0]; v.y = acc[i][j+1]; v.z = acc[i][j+2]; v.w = acc[i][j+3];
            *(float4*)(crow + j) = v;
        }
    }
}

// ---------------- attn_avg = mean over heads of P ----------------
__global__ void avg_heads(const float* __restrict__ P, float* __restrict__ out) {
    size_t i = (size_t)blockIdx.x * blockDim.x + threadIdx.x;  // float4 index
    const size_t PER_B  = (size_t)S_ * S_ / 4;
    const size_t TOTAL  = (size_t)B_ * PER_B;
    if (i >= TOTAL) return;
    size_t b   = i / PER_B;
    size_t rem = i % PER_B;
    const float4* base = (const float4*)P + b * H_ * PER_B + rem;
    float4 acc = {0.f, 0.f, 0.f, 0.f};
    #pragma unroll
    for (int h = 0; h < H_; h++) {
        float4 v = base[(size_t)h * PER_B];
        acc.x += v.x; acc.y += v.y; acc.z += v.z; acc.w += v.w;
    }
    const float s = 1.0f / 16.0f;
    acc.x *= s; acc.y *= s; acc.z *= s; acc.w *= s;
    ((float4*)out)[i] = acc;
}

// ---------------- launch ----------------
extern "C" void kernel_launch(void* const* d_in, const int* in_sizes, int n_in,
                              void* d_out, int out_size)
{
    const float* query = (const float*)d_in[0];
    const float* key   = (const float*)d_in[1];
    const float* value = (const float*)d_in[2];
    const float* Wq = (const float*)d_in[3];
    const float* bq = (const float*)d_in[4];
    const float* Wk = (const float*)d_in[5];
    const float* bk = (const float*)d_in[6];
    const float* Wv = (const float*)d_in[7];
    const float* bv = (const float*)d_in[8];
    const float* Wo = (const float*)d_in[9];
    const float* bo = (const float*)d_in[10];

    float* out      = (float*)d_out;
    float* attn_avg = out + (size_t)NTOK * E_;

    float *Qp, *Kp, *Vp, *AOp, *Pp, *ctp, *stp;
    cudaGetSymbolAddress((void**)&Qp,  d_Q);
    cudaGetSymbolAddress((void**)&Kp,  d_K);
    cudaGetSymbolAddress((void**)&Vp,  d_V);
    cudaGetSymbolAddress((void**)&AOp, d_AO);
    cudaGetSymbolAddress((void**)&Pp,  d_P);
    cudaGetSymbolAddress((void**)&ctp, d_ct);
    cudaGetSymbolAddress((void**)&stp, d_st);

    // RoPE table (independent, run first)
    build_rope_table<<<(S_*32)/256, 256>>>(ctp, stp);

    // QKV projections: C = X @ W^T + b
    dim3 g1(E_/128, NTOK/128, 1);
    sgemm_nt<0><<<g1, 256>>>(query, Wq, bq, Qp, E_, E_, E_, E_, 1.0f);
    sgemm_nt<0><<<g1, 256>>>(key,   Wk, bk, Kp, E_, E_, E_, E_, 1.0f);
    sgemm_nt<0><<<g1, 256>>>(value, Wv, bv, Vp, E_, E_, E_, E_, 1.0f);

    // RoPE on Q and K in place
    rope_apply<<<(2 * NTOK * H_ * 32) / 256, 256>>>(Qp, Kp, ctp, stp);

    // Scores: P[b,h] = 0.125 * Q_h @ K_h^T   (batched NT GEMM, K=64)
    dim3 g3(S_/128, S_/128, B_*H_);
    sgemm_nt<1><<<g3, 256>>>(Qp, Kp, nullptr, Pp, D_, E_, E_, S_, 0.125f);

    // Row softmax in place
    softmax_rows<<<B_*H_*S_, 256>>>(Pp);

    // O = P @ V per (b,h), written into AO in [B,S,E] head-merged layout
    dim3 g5(S_/128, 1, B_*H_);
    pv_gemm<<<g5, 128>>>(Pp, Vp, AOp);

    // Output projection into d_out[0 : B*S*E)
    sgemm_nt<0><<<g1, 256>>>(AOp, Wo, bo, out, E_, E_, E_, E_, 1.0f);

    // attn_avg into d_out[B*S*E : )
    avg_heads<<<(B_*S_*S_/4)/256, 256>>>(Pp, attn_avg);
}

// round 4
// speedup vs baseline: 1.0748x; 1.0748x over previous
#include <cuda_runtime.h>
#include <mma.h>
#include <math.h>

using namespace nvcuda;

#define B_ 4
#define S_ 2048
#define E_ 1024
#define H_ 16
#define D_ 64
#define NTOK (B_*S_)   // 8192

// ---------------- scratch (__device__ globals: sanctioned, no allocs) ----------------
__device__ float d_Q[(size_t)NTOK*E_];
__device__ float d_K[(size_t)NTOK*E_];
__device__ float d_V[(size_t)NTOK*E_];
__device__ float d_AO[(size_t)NTOK*E_];
__device__ float d_P[(size_t)B_*H_*S_*S_];   // 1.07 GB
__device__ float d_ct[S_*32];
__device__ float d_st[S_*32];

// ---------------- exp without MUFU, transform-proof ----------------
__device__ __forceinline__ float fast_exp(float x) {
    float t  = x * 1.44269504088896341f;
    t = fmaxf(fminf(t, 126.0f), -126.0f);
    float fn = rintf(t);
    int   n  = (int)fn;
    float f  = t - fn;
    float g  = f * 0.69314718055994531f;
    float p  = 1.0f + g*(1.0f + g*(0.5f + g*(0.16666666667f + g*(0.04166666667f + g*0.008333333333f))));
    return __int_as_float((n + 127) << 23) * p;
}

// ================= tf32 NT GEMM: C[M,N] = A[M,K] * B[N,K]^T ==================
// 128x128 block, 8 warps (2x4), warp tile 64x32, BK=32, wmma m16n16k8 tf32.
// MODE 0: plain (proj). MODE 1: batched per (b,h) scores with head offsets.
template<int MODE>
__global__ void __launch_bounds__(256) wgemm_nt(
    const float* __restrict__ A, const float* __restrict__ B,
    float* __restrict__ C, int K, int lda, int ldb, int ldc)
{
    __shared__ float As[128][36];
    __shared__ float Bs[128][36];

    const float* Ap = A;
    const float* Bp = B;
    float* Cp = C;
    if (MODE == 1) {
        int z = blockIdx.z;
        int b = z >> 4, h = z & 15;
        size_t off = (size_t)b * S_ * E_ + (size_t)h * D_;
        Ap += off; Bp += off;
        Cp += (size_t)z * S_ * S_;
    }

    int t = threadIdx.x;
    int w = t >> 5;
    int wm = w >> 2, wn = w & 3;     // 2 x 4 warps
    size_t brow = (size_t)blockIdx.y * 128;
    size_t bcol = (size_t)blockIdx.x * 128;

    wmma::fragment<wmma::accumulator, 16, 16, 8, float> cf[4][2];
    #pragma unroll
    for (int i = 0; i < 4; i++)
        #pragma unroll
        for (int j = 0; j < 2; j++) wmma::fill_fragment(cf[i][j], 0.0f);

    for (int k0 = 0; k0 < K; k0 += 32) {
        float4 av[4], bv[4];
        #pragma unroll
        for (int u = 0; u < 4; u++) {
            int i = u * 256 + t;
            int r = i >> 3, c = (i & 7) << 2;
            av[u] = *(const float4*)(Ap + (brow + r) * (size_t)lda + k0 + c);
            bv[u] = *(const float4*)(Bp + (bcol + r) * (size_t)ldb + k0 + c);
        }
        __syncthreads();
        #pragma unroll
        for (int u = 0; u < 4; u++) {
            int i = u * 256 + t;
            int r = i >> 3, c = (i & 7) << 2;
            *(float4*)&As[r][c] = av[u];
            *(float4*)&Bs[r][c] = bv[u];
        }
        __syncthreads();
        #pragma unroll
        for (int kk = 0; kk < 32; kk += 8) {
            wmma::fragment<wmma::matrix_a, 16, 16, 8, wmma::precision::tf32, wmma::row_major> af[4];
            wmma::fragment<wmma::matrix_b, 16, 16, 8, wmma::precision::tf32, wmma::col_major> bf[2];
            #pragma unroll
            for (int i = 0; i < 4; i++) {
                wmma::load_matrix_sync(af[i], &As[wm*64 + i*16][kk], 36);
                #pragma unroll
                for (int e = 0; e < af[i].num_elements; e++)
                    af[i].x[e] = wmma::__float_to_tf32(af[i].x[e]);
            }
            #pragma unroll
            for (int j = 0; j < 2; j++) {
                wmma::load_matrix_sync(bf[j], &Bs[wn*32 + j*16][kk], 36);
                #pragma unroll
                for (int e = 0; e < bf[j].num_elements; e++)
                    bf[j].x[e] = wmma::__float_to_tf32(bf[j].x[e]);
            }
            #pragma unroll
            for (int i = 0; i < 4; i++)
                #pragma unroll
                for (int j = 0; j < 2; j++)
                    wmma::mma_sync(cf[i][j], af[i], bf[j], cf[i][j]);
        }
    }

    #pragma unroll
    for (int i = 0; i < 4; i++)
        #pragma unroll
        for (int j = 0; j < 2; j++) {
            size_t row = brow + wm*64 + i*16;
            size_t col = bcol + wn*32 + j*16;
            wmma::store_matrix_sync(Cp + row * (size_t)ldc + col, cf[i][j], ldc, wmma::mem_row_major);
        }
}

// ================= tf32 NN GEMM (PV): AO[128x64 tile] = P * (V + bv) ==========
// Per (b,h): M=2048, N=64, K=2048. 8 warps (4x2), warp tile 32x32, BK=32.
__global__ void __launch_bounds__(256) wgemm_pv(
    const float* __restrict__ P, const float* __restrict__ V,
    const float* __restrict__ bv, float* __restrict__ AO)
{
    __shared__ float Ps[128][36];
    __shared__ float Vs[32][68];

    int z = blockIdx.z;
    int b = z >> 4, h = z & 15;
    const float* Pp = P + (size_t)z * S_ * S_;
    const float* Vp = V + (size_t)b * S_ * E_ + h * D_;
    float* Cp = AO + (size_t)b * S_ * E_ + h * D_;
    size_t brow = (size_t)blockIdx.x * 128;

    int t = threadIdx.x;
    int w = t >> 5;
    int wm = w >> 1, wn = w & 1;     // 4 x 2 warps

    // V bias for this head, per smem-column this thread writes
    float4 bvv[2];
    #pragma unroll
    for (int u = 0; u < 2; u++) {
        int i = u * 256 + t;
        int c = (i & 15) << 2;
        bvv[u] = *(const float4*)(bv + h * D_ + c);
    }

    wmma::fragment<wmma::accumulator, 16, 16, 8, float> cf[2][2];
    #pragma unroll
    for (int i = 0; i < 2; i++)
        #pragma unroll
        for (int j = 0; j < 2; j++) wmma::fill_fragment(cf[i][j], 0.0f);

    for (int k0 = 0; k0 < S_; k0 += 32) {
        float4 pv4[4], vv[2];
        #pragma unroll
        for (int u = 0; u < 4; u++) {
            int i = u * 256 + t;
            int r = i >> 3, c = (i & 7) << 2;
            pv4[u] = *(const float4*)(Pp + (brow + r) * (size_t)S_ + k0 + c);
        }
        #pragma unroll
        for (int u = 0; u < 2; u++) {
            int i = u * 256 + t;
            int r = i >> 4, c = (i & 15) << 2;
            float4 x = *(const float4*)(Vp + (size_t)(k0 + r) * E_ + c);
            x.x += bvv[u].x; x.y += bvv[u].y; x.z += bvv[u].z; x.w += bvv[u].w;
            vv[u] = x;
        }
        __syncthreads();
        #pragma unroll
        for (int u = 0; u < 4; u++) {
            int i = u * 256 + t;
            int r = i >> 3, c = (i & 7) << 2;
            *(float4*)&Ps[r][c] = pv4[u];
        }
        #pragma unroll
        for (int u = 0; u < 2; u++) {
            int i = u * 256 + t;
            int r = i >> 4, c = (i & 15) << 2;
            *(float4*)&Vs[r][c] = vv[u];
        }
        __syncthreads();
        #pragma unroll
        for (int kk = 0; kk < 32; kk += 8) {
            wmma::fragment<wmma::matrix_a, 16, 16, 8, wmma::precision::tf32, wmma::row_major> af[2];
            wmma::fragment<wmma::matrix_b, 16, 16, 8, wmma::precision::tf32, wmma::row_major> bf[2];
            #pragma unroll
            for (int i = 0; i < 2; i++) {
                wmma::load_matrix_sync(af[i], &Ps[wm*32 + i*16][kk], 36);
                #pragma unroll
                for (int e = 0; e < af[i].num_elements; e++)
                    af[i].x[e] = wmma::__float_to_tf32(af[i].x[e]);
            }
            #pragma unroll
            for (int j = 0; j < 2; j++) {
                wmma::load_matrix_sync(bf[j], &Vs[kk][wn*32 + j*16], 68);
                #pragma unroll
                for (int e = 0; e < bf[j].num_elements; e++)
                    bf[j].x[e] = wmma::__float_to_tf32(bf[j].x[e]);
            }
            #pragma unroll
            for (int i = 0; i < 2; i++)
                #pragma unroll
                for (int j = 0; j < 2; j++)
                    wmma::mma_sync(cf[i][j], af[i], bf[j], cf[i][j]);
        }
    }

    #pragma unroll
    for (int i = 0; i < 2; i++)
        #pragma unroll
        for (int j = 0; j < 2; j++) {
            size_t row = brow + wm*32 + i*16;
            size_t col = wn*32 + j*16;
            wmma::store_matrix_sync(Cp + row * (size_t)E_ + col, cf[i][j], E_, wmma::mem_row_major);
        }
}

// ---------------- RoPE cos/sin table (double precision, one-time) ----------------
__global__ void build_rope_table(float* __restrict__ ct, float* __restrict__ st) {
    int idx = blockIdx.x * blockDim.x + threadIdx.x;
    if (idx >= S_ * 32) return;
    int i = idx & 31;
    int s = idx >> 5;
    double expo = ((double)(2*i)) / 64.0;
    double invf = pow(10000.0, -expo);
    double f = (double)s * invf;
    ct[idx] = (float)cos(f);
    st[idx] = (float)sin(f);
}

// -------- RoPE apply, with bias add folded in; Q additionally pre-scaled by 1/8 --------
__global__ void rope_apply(float* __restrict__ Q, float* __restrict__ K,
                           const float* __restrict__ bq, const float* __restrict__ bk,
                           const float* __restrict__ ct, const float* __restrict__ st) {
    int id = blockIdx.x * blockDim.x + threadIdx.x;
    const int total = NTOK * H_ * 32;            // 4,194,304
    if (id >= 2 * total) return;
    bool isQ = (id < total);
    float* X = isQ ? Q : K;
    const float* bias = isQ ? bq : bk;
    float scl = isQ ? 0.125f : 1.0f;
    int r = isQ ? id : id - total;
    int i    = r & 31;
    int h    = (r >> 5) & 15;
    int trow = r >> 9;                           // 0..8191
    int s    = trow & (S_ - 1);
    float c  = ct[s*32 + i];
    float sn = st[s*32 + i];
    float b1 = bias[h*D_ + i];
    float b2 = bias[h*D_ + i + 32];
    float* p = X + (size_t)trow * E_ + h * D_ + i;
    float x1 = p[0] + b1, x2 = p[32] + b2;
    p[0]  = (x1 * c - x2 * sn) * scl;
    p[32] = (x2 * c + x1 * sn) * scl;
}

// ---------------- Row softmax over P (one block per 2048-wide row) ----------------
__global__ void __launch_bounds__(256) softmax_rows(float* __restrict__ P) {
    __shared__ float red[8];
    size_t row = blockIdx.x;
    float* p = P + row * (size_t)S_;
    int t = threadIdx.x;
    float4 v0 = ((float4*)p)[t];
    float4 v1 = ((float4*)p)[t + 256];

    float m = fmaxf(fmaxf(fmaxf(v0.x, v0.y), fmaxf(v0.z, v0.w)),
                    fmaxf(fmaxf(v1.x, v1.y), fmaxf(v1.z, v1.w)));
    #pragma unroll
    for (int o = 16; o; o >>= 1) m = fmaxf(m, __shfl_xor_sync(0xffffffffu, m, o));
    int warp = t >> 5, lane = t & 31;
    if (lane == 0) red[warp] = m;
    __syncthreads();
    if (t == 0) {
        float mm = red[0];
        #pragma unroll
        for (int w = 1; w < 8; w++) mm = fmaxf(mm, red[w]);
        red[0] = mm;
    }
    __syncthreads();
    m = red[0];
    __syncthreads();

    v0.x = fast_exp(v0.x - m); v0.y = fast_exp(v0.y - m);
    v0.z = fast_exp(v0.z - m); v0.w = fast_exp(v0.w - m);
    v1.x = fast_exp(v1.x - m); v1.y = fast_exp(v1.y - m);
    v1.z = fast_exp(v1.z - m); v1.w = fast_exp(v1.w - m);

    float s = v0.x + v0.y + v0.z + v0.w + v1.x + v1.y + v1.z + v1.w;
    #pragma unroll
    for (int o = 16; o; o >>= 1) s += __shfl_xor_sync(0xffffffffu, s, o);
    if (lane == 0) red[warp] = s;
    __syncthreads();
    if (t == 0) {
        float ss = red[0];
        #pragma unroll
        for (int w = 1; w < 8; w++) ss += red[w];
        red[0] = 1.0f / ss;
    }
    __syncthreads();
    float inv = red[0];

    v0.x *= inv; v0.y *= inv; v0.z *= inv; v0.w *= inv;
    v1.x *= inv; v1.y *= inv; v1.z *= inv; v1.w *= inv;
    ((float4*)p)[t]       = v0;
    ((float4*)p)[t + 256] = v1;
}

// ---------------- attn_avg = mean over heads of P ----------------
__global__ void avg_heads(const float* __restrict__ P, float* __restrict__ out) {
    size_t i = (size_t)blockIdx.x * blockDim.x + threadIdx.x;  // float4 index
    const size_t PER_B  = (size_t)S_ * S_ / 4;
    const size_t TOTAL  = (size_t)B_ * PER_B;
    if (i >= TOTAL) return;
    size_t b   = i / PER_B;
    size_t rem = i % PER_B;
    const float4* base = (const float4*)P + b * H_ * PER_B + rem;
    float4 acc = {0.f, 0.f, 0.f, 0.f};
    #pragma unroll
    for (int h = 0; h < H_; h++) {
        float4 v = base[(size_t)h * PER_B];
        acc.x += v.x; acc.y += v.y; acc.z += v.z; acc.w += v.w;
    }
    const float s = 1.0f / 16.0f;
    acc.x *= s; acc.y *= s; acc.z *= s; acc.w *= s;
    ((float4*)out)[i] = acc;
}

// ---------------- out += bo (per column) ----------------
__global__ void add_bias(float* __restrict__ out, const float* __restrict__ bo) {
    size_t i = (size_t)blockIdx.x * blockDim.x + threadIdx.x;   // float4 index
    if (i >= (size_t)NTOK * E_ / 4) return;
    int col = (int)((i << 2) & (E_ - 1));
    float4 v = ((float4*)out)[i];
    const float4 b = *(const float4*)(bo + col);
    v.x += b.x; v.y += b.y; v.z += b.z; v.w += b.w;
    ((float4*)out)[i] = v;
}

// ---------------- launch ----------------
extern "C" void kernel_launch(void* const* d_in, const int* in_sizes, int n_in,
                              void* d_out, int out_size)
{
    const float* query = (const float*)d_in[0];
    const float* key   = (const float*)d_in[1];
    const float* value = (const float*)d_in[2];
    const float* Wq = (const float*)d_in[3];
    const float* bq = (const float*)d_in[4];
    const float* Wk = (const float*)d_in[5];
    const float* bk = (const float*)d_in[6];
    const float* Wv = (const float*)d_in[7];
    const float* bv = (const float*)d_in[8];
    const float* Wo = (const float*)d_in[9];
    const float* bo = (const float*)d_in[10];

    float* out      = (float*)d_out;
    float* attn_avg = out + (size_t)NTOK * E_;

    float *Qp, *Kp, *Vp, *AOp, *Pp, *ctp, *stp;
    cudaGetSymbolAddress((void**)&Qp,  d_Q);
    cudaGetSymbolAddress((void**)&Kp,  d_K);
    cudaGetSymbolAddress((void**)&Vp,  d_V);
    cudaGetSymbolAddress((void**)&AOp, d_AO);
    cudaGetSymbolAddress((void**)&Pp,  d_P);
    cudaGetSymbolAddress((void**)&ctp, d_ct);
    cudaGetSymbolAddress((void**)&stp, d_st);

    build_rope_table<<<(S_*32)/256, 256>>>(ctp, stp);

    // QKV projections (no bias here; folded downstream)
    dim3 g1(E_/128, NTOK/128, 1);
    wgemm_nt<0><<<g1, 256>>>(query, Wq, Qp, E_, E_, E_, E_);
    wgemm_nt<0><<<g1, 256>>>(key,   Wk, Kp, E_, E_, E_, E_);
    wgemm_nt<0><<<g1, 256>>>(value, Wv, Vp, E_, E_, E_, E_);

    // RoPE (+bias, +1/8 scale on Q) in place
    rope_apply<<<(2 * NTOK * H_ * 32) / 256, 256>>>(Qp, Kp, bq, bk, ctp, stp);

    // Scores: P[b,h] = Q_h @ K_h^T (scale pre-folded into Q)
    dim3 g3(S_/128, S_/128, B_*H_);
    wgemm_nt<1><<<g3, 256>>>(Qp, Kp, Pp, D_, E_, E_, S_);

    // Row softmax in place
    softmax_rows<<<B_*H_*S_, 256>>>(Pp);

    // O = P @ (V + bv) per (b,h)
    dim3 g5(S_/128, 1, B_*H_);
    wgemm_pv<<<g5, 256>>>(Pp, Vp, bv, AOp);

    // Output projection + bias
    wgemm_nt<0><<<g1, 256>>>(AOp, Wo, out, E_, E_, E_, E_);
    add_bias<<<(NTOK*E_/4 + 255)/256, 256>>>(out, bo);

    // attn_avg
    avg_heads<<<(B_*S_*S_/4)/256, 256>>>(Pp, attn_avg);
}

// round 8
// speedup vs baseline: 3.6654x; 3.4103x over previous
#include <cuda_runtime.h>
#include <cuda_fp16.h>
#include <mma.h>
#include <math.h>

using namespace nvcuda;

#define B_ 4
#define S_ 2048
#define E_ 1024
#define H_ 16
#define D_ 64
#define NTOK (B_*S_)   // 8192

// ---------------- scratch (__device__ globals) ----------------
__device__ float  d_Q[(size_t)NTOK*E_];
__device__ float  d_K[(size_t)NTOK*E_];
__device__ float  d_V[(size_t)NTOK*E_];
__device__ float  d_AO[(size_t)NTOK*E_];
__device__ __half d_E[(size_t)B_*H_*S_*S_];    // 536 MB: exp(scores), unnormalized
__device__ float  d_irs[(size_t)B_*H_*S_];     // 1/rowsum
__device__ float  d_ct[S_*32];
__device__ float  d_st[S_*32];

// ---------------- FMA-only exp (B300 MUFU is slow: rt_SMSP=8) ----------------
__device__ __forceinline__ float fast_exp(float x) {
    float t  = x * 1.44269504088896341f;
    t = fmaxf(fminf(t, 126.0f), -126.0f);
    float fn = rintf(t);
    int   n  = (int)fn;
    float f  = t - fn;
    float g  = f * 0.69314718055994531f;
    float p  = 1.0f + g*(1.0f + g*(0.5f + g*(0.16666666667f + g*(0.04166666667f + g*0.008333333333f))));
    return __int_as_float((n + 127) << 23) * p;
}

// ============ NT GEMM, fp32 gmem in/out, fp16 MMA: C = A * B^T ============
// 128x128 tile, BK=32, 8 warps (2x4), warp 64x32, m16n16k16.
// Single fp16 rounding at smem store (precision == tf32-at-MMA).
__global__ void __launch_bounds__(256,2) hgemm_proj(
    const float* __restrict__ A, const float* __restrict__ B,
    float* __restrict__ C, int K, int lda, int ldb, int ldc)
{
    __shared__ __half As[128][40];
    __shared__ __half Bs[128][40];

    int t = threadIdx.x;
    int w = t >> 5;
    int wm = w >> 2, wn = w & 3;
    size_t brow = (size_t)blockIdx.y * 128;
    size_t bcol = (size_t)blockIdx.x * 128;

    wmma::fragment<wmma::accumulator,16,16,16,float> cf[4][2];
    #pragma unroll
    for (int i = 0; i < 4; i++)
        #pragma unroll
        for (int j = 0; j < 2; j++) wmma::fill_fragment(cf[i][j], 0.0f);

    for (int k0 = 0; k0 < K; k0 += 32) {
        float4 av4[4], bv4[4];
        #pragma unroll
        for (int u = 0; u < 4; u++) {
            int i = u*256 + t, r = i >> 3, c4 = (i & 7) << 2;
            av4[u] = *(const float4*)(A + (brow + r) * (size_t)lda + k0 + c4);
            bv4[u] = *(const float4*)(B + (bcol + r) * (size_t)ldb + k0 + c4);
        }
        __syncthreads();
        #pragma unroll
        for (int u = 0; u < 4; u++) {
            int i = u*256 + t, r = i >> 3, c4 = (i & 7) << 2;
            __half ha[4], hb[4];
            ha[0]=__float2half_rn(av4[u].x); ha[1]=__float2half_rn(av4[u].y);
            ha[2]=__float2half_rn(av4[u].z); ha[3]=__float2half_rn(av4[u].w);
            hb[0]=__float2half_rn(bv4[u].x); hb[1]=__float2half_rn(bv4[u].y);
            hb[2]=__float2half_rn(bv4[u].z); hb[3]=__float2half_rn(bv4[u].w);
            *(uint2*)&As[r][c4] = *(uint2*)ha;
            *(uint2*)&Bs[r][c4] = *(uint2*)hb;
        }
        __syncthreads();
        #pragma unroll
        for (int kk = 0; kk < 32; kk += 16) {
            wmma::fragment<wmma::matrix_a,16,16,16,__half,wmma::row_major> af[4];
            wmma::fragment<wmma::matrix_b,16,16,16,__half,wmma::col_major> bf[2];
            #pragma unroll
            for (int i = 0; i < 4; i++) wmma::load_matrix_sync(af[i], &As[wm*64 + i*16][kk], 40);
            #pragma unroll
            for (int j = 0; j < 2; j++) wmma::load_matrix_sync(bf[j], &Bs[wn*32 + j*16][kk], 40);
            #pragma unroll
            for (int i = 0; i < 4; i++)
                #pragma unroll
                for (int j = 0; j < 2; j++)
                    wmma::mma_sync(cf[i][j], af[i], bf[j], cf[i][j]);
        }
    }

    #pragma unroll
    for (int i = 0; i < 4; i++)
        #pragma unroll
        for (int j = 0; j < 2; j++) {
            size_t row = brow + wm*64 + i*16;
            size_t col = bcol + wn*32 + j*16;
            wmma::store_matrix_sync(C + row * (size_t)ldc + col, cf[i][j], ldc, wmma::mem_row_major);
        }
}

// ============ Scores+exp: E[b,h] = exp(Q_h @ K_h^T) — fp32 in, fp16 E out ============
__global__ void __launch_bounds__(256,2) hgemm_scores(
    const float* __restrict__ Q, const float* __restrict__ Kf,
    __half* __restrict__ Eg)
{
    __shared__ __half As[128][72];
    __shared__ __half Bs[128][72];
    __shared__ float  stg[8][16][20];

    int z = blockIdx.z, b = z >> 4, h = z & 15;
    const float* Ap = Q  + (size_t)b * S_ * E_ + h * D_;
    const float* Bp = Kf + (size_t)b * S_ * E_ + h * D_;
    __half* Cp = Eg + (size_t)z * S_ * S_;

    int t = threadIdx.x;
    int w = t >> 5;
    int wm = w >> 2, wn = w & 3;
    size_t brow = (size_t)blockIdx.y * 128;
    size_t bcol = (size_t)blockIdx.x * 128;

    // load 128x64 fp32 of Q and K, convert to fp16 in smem
    #pragma unroll
    for (int u = 0; u < 8; u++) {
        int i = u*256 + t;
        int r = i >> 4, c4 = (i & 15) << 2;
        float4 a = *(const float4*)(Ap + (brow + r) * (size_t)E_ + c4);
        float4 bb = *(const float4*)(Bp + (bcol + r) * (size_t)E_ + c4);
        __half ha[4], hb[4];
        ha[0]=__float2half_rn(a.x);  ha[1]=__float2half_rn(a.y);
        ha[2]=__float2half_rn(a.z);  ha[3]=__float2half_rn(a.w);
        hb[0]=__float2half_rn(bb.x); hb[1]=__float2half_rn(bb.y);
        hb[2]=__float2half_rn(bb.z); hb[3]=__float2half_rn(bb.w);
        *(uint2*)&As[r][c4] = *(uint2*)ha;
        *(uint2*)&Bs[r][c4] = *(uint2*)hb;
    }
    __syncthreads();

    wmma::fragment<wmma::accumulator,16,16,16,float> cf[4][2];
    #pragma unroll
    for (int i = 0; i < 4; i++)
        #pragma unroll
        for (int j = 0; j < 2; j++) wmma::fill_fragment(cf[i][j], 0.0f);

    #pragma unroll
    for (int kk = 0; kk < 64; kk += 16) {
        wmma::fragment<wmma::matrix_a,16,16,16,__half,wmma::row_major> af[4];
        wmma::fragment<wmma::matrix_b,16,16,16,__half,wmma::col_major> bf[2];
        #pragma unroll
        for (int i = 0; i < 4; i++) wmma::load_matrix_sync(af[i], &As[wm*64 + i*16][kk], 72);
        #pragma unroll
        for (int j = 0; j < 2; j++) wmma::load_matrix_sync(bf[j], &Bs[wn*32 + j*16][kk], 72);
        #pragma unroll
        for (int i = 0; i < 4; i++)
            #pragma unroll
            for (int j = 0; j < 2; j++)
                wmma::mma_sync(cf[i][j], af[i], bf[j], cf[i][j]);
    }

    int lane = t & 31;
    int r = lane >> 1, c = (lane & 1) * 8;
    #pragma unroll
    for (int i = 0; i < 4; i++)
        #pragma unroll
        for (int j = 0; j < 2; j++) {
            size_t row = brow + wm*64 + i*16;
            size_t col = bcol + wn*32 + j*16;
            wmma::store_matrix_sync(&stg[w][0][0], cf[i][j], 20, wmma::mem_row_major);
            __syncwarp();
            __half hh[8];
            #pragma unroll
            for (int e = 0; e < 8; e++) {
                float s = fminf(fmaxf(stg[w][r][c+e], -20.0f), 8.0f);
                hh[e] = __float2half_rn(fast_exp(s));
            }
            *(uint4*)(Cp + (row + r) * (size_t)S_ + col + c) = *(uint4*)hh;
            __syncwarp();
        }
}

// ============ PV: AO = (E @ (V + bv)) / rowsum(E); E fp16, V fp32, AO fp32 ============
__global__ void __launch_bounds__(256,2) hgemm_pv(
    const __half* __restrict__ Eg, const float* __restrict__ Vf,
    const float* __restrict__ bv, float* __restrict__ AO,
    float* __restrict__ irs)
{
    __shared__ __half Es[128][72];
    __shared__ __half Vs[64][72];
    __shared__ float  stg[8][16][20];
    __shared__ float  rbuf[128][8];
    __shared__ float  rsinv[128];

    int z = blockIdx.z, b = z >> 4, h = z & 15;
    const __half* Ep = Eg + (size_t)z * S_ * S_;
    const float* Vp = Vf + (size_t)b * S_ * E_ + h * D_;
    float* Cp = AO + (size_t)b * S_ * E_ + h * D_;
    size_t brow = (size_t)blockIdx.x * 128;

    int t = threadIdx.x;
    int w = t >> 5;
    int wm = w >> 1, wn = w & 1;          // 4 x 2 warps, warp 32x32
    int r0 = t >> 3, c8 = (t & 7) << 3;
    int rv = t >> 4, cv4 = (t & 15) << 2; // V loader: 64 rows x 16 float4

    float bvv4[4];
    #pragma unroll
    for (int e = 0; e < 4; e++) bvv4[e] = bv[h*D_ + cv4 + e];

    float psum[4] = {0.f, 0.f, 0.f, 0.f};
    wmma::fragment<wmma::accumulator,16,16,16,float> cf[2][2];
    #pragma unroll
    for (int i = 0; i < 2; i++)
        #pragma unroll
        for (int j = 0; j < 2; j++) wmma::fill_fragment(cf[i][j], 0.0f);

    for (int k0 = 0; k0 < S_; k0 += 64) {
        uint4 eraw[4];
        __half vh[4][4];
        #pragma unroll
        for (int u = 0; u < 4; u++) {
            int r = u*32 + r0;
            eraw[u] = *(const uint4*)(Ep + (brow + r) * (size_t)S_ + k0 + c8);
            const __half* hp = (const __half*)&eraw[u];
            #pragma unroll
            for (int e = 0; e < 8; e++) psum[u] += __half2float(hp[e]);
        }
        #pragma unroll
        for (int u = 0; u < 4; u++) {
            int r = u*16 + rv;
            float4 x = *(const float4*)(Vp + (size_t)(k0 + r) * E_ + cv4);
            vh[u][0] = __float2half_rn(x.x + bvv4[0]);
            vh[u][1] = __float2half_rn(x.y + bvv4[1]);
            vh[u][2] = __float2half_rn(x.z + bvv4[2]);
            vh[u][3] = __float2half_rn(x.w + bvv4[3]);
        }
        __syncthreads();
        #pragma unroll
        for (int u = 0; u < 4; u++) *(uint4*)&Es[u*32 + r0][c8] = eraw[u];
        #pragma unroll
        for (int u = 0; u < 4; u++) *(uint2*)&Vs[u*16 + rv][cv4] = *(uint2*)vh[u];
        __syncthreads();
        #pragma unroll
        for (int kk = 0; kk < 64; kk += 16) {
            wmma::fragment<wmma::matrix_a,16,16,16,__half,wmma::row_major> af[2];
            wmma::fragment<wmma::matrix_b,16,16,16,__half,wmma::row_major> bf[2];
            #pragma unroll
            for (int i = 0; i < 2; i++) wmma::load_matrix_sync(af[i], &Es[wm*32 + i*16][kk], 72);
            #pragma unroll
            for (int j = 0; j < 2; j++) wmma::load_matrix_sync(bf[j], &Vs[kk][wn*32 + j*16], 72);
            #pragma unroll
            for (int i = 0; i < 2; i++)
                #pragma unroll
                for (int j = 0; j < 2; j++)
                    wmma::mma_sync(cf[i][j], af[i], bf[j], cf[i][j]);
        }
    }

    // row sums -> 1/sum
    #pragma unroll
    for (int u = 0; u < 4; u++) rbuf[u*32 + r0][t & 7] = psum[u];
    __syncthreads();
    if (t < 128) {
        float s = rbuf[t][0]+rbuf[t][1]+rbuf[t][2]+rbuf[t][3]
                + rbuf[t][4]+rbuf[t][5]+rbuf[t][6]+rbuf[t][7];
        float inv = 1.0f / s;
        rsinv[t] = inv;
        irs[(size_t)z * S_ + brow + t] = inv;
    }
    __syncthreads();

    int lane = t & 31;
    int r = lane >> 1, c = (lane & 1) * 8;
    #pragma unroll
    for (int i = 0; i < 2; i++)
        #pragma unroll
        for (int j = 0; j < 2; j++) {
            int rl = wm*32 + i*16;
            wmma::store_matrix_sync(&stg[w][0][0], cf[i][j], 20, wmma::mem_row_major);
            __syncwarp();
            float sc = rsinv[rl + r];
            float* gp = Cp + (brow + rl + r) * (size_t)E_ + wn*32 + j*16 + c;
            float4 o0, o1;
            o0.x = stg[w][r][c+0]*sc; o0.y = stg[w][r][c+1]*sc;
            o0.z = stg[w][r][c+2]*sc; o0.w = stg[w][r][c+3]*sc;
            o1.x = stg[w][r][c+4]*sc; o1.y = stg[w][r][c+5]*sc;
            o1.z = stg[w][r][c+6]*sc; o1.w = stg[w][r][c+7]*sc;
            *(float4*)gp = o0;
            *(float4*)(gp+4) = o1;
            __syncwarp();
        }
}

// ---------------- RoPE cos/sin table (double precision, one-time) ----------------
__global__ void build_rope_table(float* __restrict__ ct, float* __restrict__ st) {
    int idx = blockIdx.x * blockDim.x + threadIdx.x;
    if (idx >= S_ * 32) return;
    int i = idx & 31;
    int s = idx >> 5;
    double expo = ((double)(2*i)) / 64.0;
    double invf = pow(10000.0, -expo);
    double f = (double)s * invf;
    ct[idx] = (float)cos(f);
    st[idx] = (float)sin(f);
}

// -------- RoPE on fp32 Q/K, bias folded, Q pre-scaled by 1/8 --------
__global__ void rope_apply(float* __restrict__ Q, float* __restrict__ K,
                           const float* __restrict__ bq, const float* __restrict__ bk,
                           const float* __restrict__ ct, const float* __restrict__ st) {
    int id = blockIdx.x * blockDim.x + threadIdx.x;
    const int total = NTOK * H_ * 32;            // 4,194,304
    if (id >= 2 * total) return;
    bool isQ = (id < total);
    float* X = isQ ? Q : K;
    const float* bias = isQ ? bq : bk;
    float scl = isQ ? 0.125f : 1.0f;
    int r = isQ ? id : id - total;
    int i    = r & 31;
    int h    = (r >> 5) & 15;
    int trow = r >> 9;
    int s    = trow & (S_ - 1);
    float c  = ct[s*32 + i];
    float sn = st[s*32 + i];
    float b1 = bias[h*D_ + i];
    float b2 = bias[h*D_ + i + 32];
    float* p = X + (size_t)trow * E_ + h * D_ + i;
    float x1 = p[0] + b1, x2 = p[32] + b2;
    p[0]  = (x1 * c - x2 * sn) * scl;
    p[32] = (x2 * c + x1 * sn) * scl;
}

// ---------------- attn_avg = mean over heads of E*irs ----------------
__global__ void avg_heads(const __half* __restrict__ Eg, const float* __restrict__ irs,
                          float* __restrict__ out) {
    size_t i = (size_t)blockIdx.x * blockDim.x + threadIdx.x;    // 8-elem group
    const size_t TOT = (size_t)B_ * S_ * (S_/8);
    if (i >= TOT) return;
    size_t k8 = i % (S_/8);
    size_t q  = (i / (S_/8)) % S_;
    size_t b  = i / ((size_t)(S_/8) * S_);
    float acc[8] = {0,0,0,0,0,0,0,0};
    #pragma unroll
    for (int h = 0; h < H_; h++) {
        size_t zh = b * H_ + h;
        uint4 raw = *(const uint4*)(Eg + (zh * S_ + q) * (size_t)S_ + k8*8);
        const __half* hp = (const __half*)&raw;
        float inv = irs[zh * S_ + q];
        #pragma unroll
        for (int e = 0; e < 8; e++)
            acc[e] += __half2float(hp[e]) * inv;
    }
    float* op = out + (b * S_ + q) * (size_t)S_ + k8*8;
    #pragma unroll
    for (int e = 0; e < 8; e++) op[e] = acc[e] * (1.0f/16.0f);
}

// ---------------- out += bo ----------------
__global__ void add_bias(float* __restrict__ out, const float* __restrict__ bo) {
    size_t i = (size_t)blockIdx.x * blockDim.x + threadIdx.x;
    if (i >= (size_t)NTOK * E_ / 4) return;
    int col = (int)((i << 2) & (E_ - 1));
    float4 v = ((float4*)out)[i];
    const float4 bb = *(const float4*)(bo + col);
    v.x += bb.x; v.y += bb.y; v.z += bb.z; v.w += bb.w;
    ((float4*)out)[i] = v;
}

// ---------------- launch ----------------
extern "C" void kernel_launch(void* const* d_in, const int* in_sizes, int n_in,
                              void* d_out, int out_size)
{
    const float* query = (const float*)d_in[0];
    const float* key   = (const float*)d_in[1];
    const float* value = (const float*)d_in[2];
    const float* Wq = (const float*)d_in[3];
    const float* bq = (const float*)d_in[4];
    const float* Wk = (const float*)d_in[5];
    const float* bk = (const float*)d_in[6];
    const float* Wv = (const float*)d_in[7];
    const float* bv = (const float*)d_in[8];
    const float* Wo = (const float*)d_in[9];
    const float* bo = (const float*)d_in[10];

    float* out      = (float*)d_out;
    float* attn_avg = out + (size_t)NTOK * E_;

    __half *Eh;
    float *Qp, *Kp, *Vp, *AOp, *irs, *ctp, *stp;
    cudaGetSymbolAddress((void**)&Qp,  d_Q);
    cudaGetSymbolAddress((void**)&Kp,  d_K);
    cudaGetSymbolAddress((void**)&Vp,  d_V);
    cudaGetSymbolAddress((void**)&Eh,  d_E);
    cudaGetSymbolAddress((void**)&AOp, d_AO);
    cudaGetSymbolAddress((void**)&irs, d_irs);
    cudaGetSymbolAddress((void**)&ctp, d_ct);
    cudaGetSymbolAddress((void**)&stp, d_st);

    build_rope_table<<<(S_*32)/256, 256>>>(ctp, stp);

    // QKV projections: fp32 in/out, fp16 MMA inside
    dim3 g1(E_/128, NTOK/128, 1);
    hgemm_proj<<<g1, 256>>>(query, Wq, Qp, E_, E_, E_, E_);
    hgemm_proj<<<g1, 256>>>(key,   Wk, Kp, E_, E_, E_, E_);
    hgemm_proj<<<g1, 256>>>(value, Wv, Vp, E_, E_, E_, E_);

    // RoPE (+bias, +1/8 on Q), fp32 in place
    rope_apply<<<(2 * NTOK * H_ * 32) / 256, 256>>>(Qp, Kp, bq, bk, ctp, stp);

    // E = exp(scores), fp16 out
    dim3 g3(S_/128, S_/128, B_*H_);
    hgemm_scores<<<g3, 256>>>(Qp, Kp, Eh);

    // AO = (E @ (V+bv)) / rowsum, fp32
    dim3 g5(S_/128, 1, B_*H_);
    hgemm_pv<<<g5, 256>>>(Eh, Vp, bv, AOp, irs);

    // Output projection + bias
    hgemm_proj<<<g1, 256>>>(AOp, Wo, out, E_, E_, E_, E_);
    add_bias<<<(NTOK*E_/4 + 255)/256, 256>>>(out, bo);

    // attn_avg from E + inverse row sums
    avg_heads<<<(B_*S_*(S_/8) + 255)/256, 256>>>(Eh, irs, attn_avg);
}

// round 11
// speedup vs baseline: 3.8261x; 1.0439x over previous
#include <cuda_runtime.h>
#include <cuda_fp16.h>
#include <mma.h>
#include <math.h>

using namespace nvcuda;

#define B_ 4
#define S_ 2048
#define E_ 1024
#define H_ 16
#define D_ 64
#define NTOK (B_*S_)   // 8192

// ---------------- scratch (__device__ globals) ----------------
__device__ float  d_Q[(size_t)NTOK*E_];
__device__ float  d_K[(size_t)NTOK*E_];
__device__ float  d_V[(size_t)NTOK*E_];
__device__ float  d_AO[(size_t)NTOK*E_];
__device__ __half d_E[(size_t)B_*H_*S_*S_];    // 536 MB: exp(scores), unnormalized
__device__ float  d_irs[(size_t)B_*H_*S_];     // 1/rowsum
__device__ float  d_ct[S_*32];
__device__ float  d_st[S_*32];

// ---------------- FMA-only exp (B300 MUFU is slow: rt_SMSP=8) ----------------
__device__ __forceinline__ float fast_exp(float x) {
    float t  = x * 1.44269504088896341f;
    t = fmaxf(fminf(t, 126.0f), -126.0f);
    float fn = rintf(t);
    int   n  = (int)fn;
    float f  = t - fn;
    float g  = f * 0.69314718055994531f;
    float p  = 1.0f + g*(1.0f + g*(0.5f + g*(0.16666666667f + g*(0.04166666667f + g*0.008333333333f))));
    return __int_as_float((n + 127) << 23) * p;
}

// ============ NT GEMM, fp32 gmem in/out, fp16 MMA, 2-stage pipelined ============
// 128x128 tile, BK=32, 8 warps (2x4), warp 64x32, m16n16k16.
__global__ void __launch_bounds__(256,2) hgemm_proj(
    const float* __restrict__ A, const float* __restrict__ B,
    float* __restrict__ C, int K, int lda, int ldb, int ldc)
{
    __shared__ __half As[2][128][40];
    __shared__ __half Bs[2][128][40];

    int t = threadIdx.x;
    int w = t >> 5;
    int wm = w >> 2, wn = w & 3;
    size_t brow = (size_t)blockIdx.y * 128;
    size_t bcol = (size_t)blockIdx.x * 128;
    int lr = t >> 3, lc4 = (t & 7) << 2;

    wmma::fragment<wmma::accumulator,16,16,16,float> cf[4][2];
    #pragma unroll
    for (int i = 0; i < 4; i++)
        #pragma unroll
        for (int j = 0; j < 2; j++) wmma::fill_fragment(cf[i][j], 0.0f);

    float4 av4[4], bv4[4];

    // prologue: tile 0
    #pragma unroll
    for (int u = 0; u < 4; u++) {
        int r = u*32 + lr;
        av4[u] = *(const float4*)(A + (brow + r) * (size_t)lda + lc4);
        bv4[u] = *(const float4*)(B + (bcol + r) * (size_t)ldb + lc4);
    }
    #pragma unroll
    for (int u = 0; u < 4; u++) {
        int r = u*32 + lr;
        __half ha[4], hb[4];
        ha[0]=__float2half_rn(av4[u].x); ha[1]=__float2half_rn(av4[u].y);
        ha[2]=__float2half_rn(av4[u].z); ha[3]=__float2half_rn(av4[u].w);
        hb[0]=__float2half_rn(bv4[u].x); hb[1]=__float2half_rn(bv4[u].y);
        hb[2]=__float2half_rn(bv4[u].z); hb[3]=__float2half_rn(bv4[u].w);
        *(uint2*)&As[0][r][lc4] = *(uint2*)ha;
        *(uint2*)&Bs[0][r][lc4] = *(uint2*)hb;
    }
    __syncthreads();

    int nit = K >> 5;
    for (int it = 0; it < nit; it++) {
        int cur = it & 1;
        if (it + 1 < nit) {
            int k0 = (it + 1) << 5;
            #pragma unroll
            for (int u = 0; u < 4; u++) {
                int r = u*32 + lr;
                av4[u] = *(const float4*)(A + (brow + r) * (size_t)lda + k0 + lc4);
                bv4[u] = *(const float4*)(B + (bcol + r) * (size_t)ldb + k0 + lc4);
            }
        }
        #pragma unroll
        for (int kk = 0; kk < 32; kk += 16) {
            wmma::fragment<wmma::matrix_a,16,16,16,__half,wmma::row_major> af[4];
            wmma::fragment<wmma::matrix_b,16,16,16,__half,wmma::col_major> bf[2];
            #pragma unroll
            for (int i = 0; i < 4; i++) wmma::load_matrix_sync(af[i], &As[cur][wm*64 + i*16][kk], 40);
            #pragma unroll
            for (int j = 0; j < 2; j++) wmma::load_matrix_sync(bf[j], &Bs[cur][wn*32 + j*16][kk], 40);
            #pragma unroll
            for (int i = 0; i < 4; i++)
                #pragma unroll
                for (int j = 0; j < 2; j++)
                    wmma::mma_sync(cf[i][j], af[i], bf[j], cf[i][j]);
        }
        if (it + 1 < nit) {
            int nxt = 1 - cur;
            #pragma unroll
            for (int u = 0; u < 4; u++) {
                int r = u*32 + lr;
                __half ha[4], hb[4];
                ha[0]=__float2half_rn(av4[u].x); ha[1]=__float2half_rn(av4[u].y);
                ha[2]=__float2half_rn(av4[u].z); ha[3]=__float2half_rn(av4[u].w);
                hb[0]=__float2half_rn(bv4[u].x); hb[1]=__float2half_rn(bv4[u].y);
                hb[2]=__float2half_rn(bv4[u].z); hb[3]=__float2half_rn(bv4[u].w);
                *(uint2*)&As[nxt][r][lc4] = *(uint2*)ha;
                *(uint2*)&Bs[nxt][r][lc4] = *(uint2*)hb;
            }
            __syncthreads();
        }
    }

    #pragma unroll
    for (int i = 0; i < 4; i++)
        #pragma unroll
        for (int j = 0; j < 2; j++) {
            size_t row = brow + wm*64 + i*16;
            size_t col = bcol + wn*32 + j*16;
            wmma::store_matrix_sync(C + row * (size_t)ldc + col, cf[i][j], ldc, wmma::mem_row_major);
        }
}

// ============ Scores+exp: E[b,h] = exp(Q_h @ K_h^T) — fp32 in, fp16 E out ============
__global__ void __launch_bounds__(256,2) hgemm_scores(
    const float* __restrict__ Q, const float* __restrict__ Kf,
    __half* __restrict__ Eg)
{
    __shared__ __half As[128][72];
    __shared__ __half Bs[128][72];
    __shared__ float  stg[8][16][20];

    int z = blockIdx.z, b = z >> 4, h = z & 15;
    const float* Ap = Q  + (size_t)b * S_ * E_ + h * D_;
    const float* Bp = Kf + (size_t)b * S_ * E_ + h * D_;
    __half* Cp = Eg + (size_t)z * S_ * S_;

    int t = threadIdx.x;
    int w = t >> 5;
    int wm = w >> 2, wn = w & 3;
    size_t brow = (size_t)blockIdx.y * 128;
    size_t bcol = (size_t)blockIdx.x * 128;

    #pragma unroll
    for (int u = 0; u < 8; u++) {
        int i = u*256 + t;
        int r = i >> 4, c4 = (i & 15) << 2;
        float4 a = *(const float4*)(Ap + (brow + r) * (size_t)E_ + c4);
        float4 bb = *(const float4*)(Bp + (bcol + r) * (size_t)E_ + c4);
        __half ha[4], hb[4];
        ha[0]=__float2half_rn(a.x);  ha[1]=__float2half_rn(a.y);
        ha[2]=__float2half_rn(a.z);  ha[3]=__float2half_rn(a.w);
        hb[0]=__float2half_rn(bb.x); hb[1]=__float2half_rn(bb.y);
        hb[2]=__float2half_rn(bb.z); hb[3]=__float2half_rn(bb.w);
        *(uint2*)&As[r][c4] = *(uint2*)ha;
        *(uint2*)&Bs[r][c4] = *(uint2*)hb;
    }
    __syncthreads();

    wmma::fragment<wmma::accumulator,16,16,16,float> cf[4][2];
    #pragma unroll
    for (int i = 0; i < 4; i++)
        #pragma unroll
        for (int j = 0; j < 2; j++) wmma::fill_fragment(cf[i][j], 0.0f);

    #pragma unroll
    for (int kk = 0; kk < 64; kk += 16) {
        wmma::fragment<wmma::matrix_a,16,16,16,__half,wmma::row_major> af[4];
        wmma::fragment<wmma::matrix_b,16,16,16,__half,wmma::col_major> bf[2];
        #pragma unroll
        for (int i = 0; i < 4; i++) wmma::load_matrix_sync(af[i], &As[wm*64 + i*16][kk], 72);
        #pragma unroll
        for (int j = 0; j < 2; j++) wmma::load_matrix_sync(bf[j], &Bs[wn*32 + j*16][kk], 72);
        #pragma unroll
        for (int i = 0; i < 4; i++)
            #pragma unroll
            for (int j = 0; j < 2; j++)
                wmma::mma_sync(cf[i][j], af[i], bf[j], cf[i][j]);
    }

    int lane = t & 31;
    int r = lane >> 1, c = (lane & 1) * 8;
    #pragma unroll
    for (int i = 0; i < 4; i++)
        #pragma unroll
        for (int j = 0; j < 2; j++) {
            size_t row = brow + wm*64 + i*16;
            size_t col = bcol + wn*32 + j*16;
            wmma::store_matrix_sync(&stg[w][0][0], cf[i][j], 20, wmma::mem_row_major);
            __syncwarp();
            __half hh[8];
            #pragma unroll
            for (int e = 0; e < 8; e++) {
                float s = fminf(fmaxf(stg[w][r][c+e], -20.0f), 8.0f);
                hh[e] = __float2half_rn(fast_exp(s));
            }
            *(uint4*)(Cp + (row + r) * (size_t)S_ + col + c) = *(uint4*)hh;
            __syncwarp();
        }
}

// ============ PV: AO = (E @ (V + bv)) / rowsum(E); 2-stage pipelined BK=32 ============
__global__ void __launch_bounds__(256,2) hgemm_pv(
    const __half* __restrict__ Eg, const float* __restrict__ Vf,
    const float* __restrict__ bv, float* __restrict__ AO,
    float* __restrict__ irs)
{
    __shared__ __half Es[2][128][40];
    __shared__ __half Vs[2][32][72];
    __shared__ float  rbuf[128][4];
    __shared__ float  rsinv[128];

    int z = blockIdx.z, b = z >> 4, h = z & 15;
    const __half* Ep = Eg + (size_t)z * S_ * S_;
    const float* Vp = Vf + (size_t)b * S_ * E_ + h * D_;
    float* Cp = AO + (size_t)b * S_ * E_ + h * D_;
    size_t brow = (size_t)blockIdx.x * 128;

    int t = threadIdx.x;
    int w = t >> 5;
    int wm = w >> 1, wn = w & 1;          // 4 x 2 warps, warp 32x32
    int re = t >> 2, ce = (t & 3) << 3;   // E loader: rows re, re+64; cols ce..ce+7
    int rv = t >> 4, cv4 = (t & 15) << 2; // V loader: rows rv, rv+16

    float bvv4[4];
    #pragma unroll
    for (int e = 0; e < 4; e++) bvv4[e] = bv[h*D_ + cv4 + e];

    float psum[2] = {0.f, 0.f};
    wmma::fragment<wmma::accumulator,16,16,16,float> cf[2][2];
    #pragma unroll
    for (int i = 0; i < 2; i++)
        #pragma unroll
        for (int j = 0; j < 2; j++) wmma::fill_fragment(cf[i][j], 0.0f);

    uint4 eraw[2];
    float4 vraw[2];

    // prologue: tile 0
    eraw[0] = *(const uint4*)(Ep + (brow + re)      * (size_t)S_ + ce);
    eraw[1] = *(const uint4*)(Ep + (brow + 64 + re) * (size_t)S_ + ce);
    vraw[0] = *(const float4*)(Vp + (size_t)(rv)      * E_ + cv4);
    vraw[1] = *(const float4*)(Vp + (size_t)(16 + rv) * E_ + cv4);
    {
        const __half* h0 = (const __half*)&eraw[0];
        const __half* h1 = (const __half*)&eraw[1];
        #pragma unroll
        for (int e = 0; e < 8; e++) { psum[0] += __half2float(h0[e]); psum[1] += __half2float(h1[e]); }
        *(uint4*)&Es[0][re][ce]      = eraw[0];
        *(uint4*)&Es[0][64 + re][ce] = eraw[1];
        __half v0[4], v1[4];
        v0[0]=__float2half_rn(vraw[0].x+bvv4[0]); v0[1]=__float2half_rn(vraw[0].y+bvv4[1]);
        v0[2]=__float2half_rn(vraw[0].z+bvv4[2]); v0[3]=__float2half_rn(vraw[0].w+bvv4[3]);
        v1[0]=__float2half_rn(vraw[1].x+bvv4[0]); v1[1]=__float2half_rn(vraw[1].y+bvv4[1]);
        v1[2]=__float2half_rn(vraw[1].z+bvv4[2]); v1[3]=__float2half_rn(vraw[1].w+bvv4[3]);
        *(uint2*)&Vs[0][rv][cv4]      = *(uint2*)v0;
        *(uint2*)&Vs[0][16 + rv][cv4] = *(uint2*)v1;
    }
    __syncthreads();

    const int NIT = S_ >> 5;   // 64
    for (int it = 0; it < NIT; it++) {
        int cur = it & 1;
        if (it + 1 < NIT) {
            int k0 = (it + 1) << 5;
            eraw[0] = *(const uint4*)(Ep + (brow + re)      * (size_t)S_ + k0 + ce);
            eraw[1] = *(const uint4*)(Ep + (brow + 64 + re) * (size_t)S_ + k0 + ce);
            vraw[0] = *(const float4*)(Vp + (size_t)(k0 + rv)      * E_ + cv4);
            vraw[1] = *(const float4*)(Vp + (size_t)(k0 + 16 + rv) * E_ + cv4);
        }
        #pragma unroll
        for (int kk = 0; kk < 32; kk += 16) {
            wmma::fragment<wmma::matrix_a,16,16,16,__half,wmma::row_major> af[2];
            wmma::fragment<wmma::matrix_b,16,16,16,__half,wmma::row_major> bf[2];
            #pragma unroll
            for (int i = 0; i < 2; i++) wmma::load_matrix_sync(af[i], &Es[cur][wm*32 + i*16][kk], 40);
            #pragma unroll
            for (int j = 0; j < 2; j++) wmma::load_matrix_sync(bf[j], &Vs[cur][kk][wn*32 + j*16], 72);
            #pragma unroll
            for (int i = 0; i < 2; i++)
                #pragma unroll
                for (int j = 0; j < 2; j++)
                    wmma::mma_sync(cf[i][j], af[i], bf[j], cf[i][j]);
        }
        if (it + 1 < NIT) {
            int nxt = 1 - cur;
            const __half* h0 = (const __half*)&eraw[0];
            const __half* h1 = (const __half*)&eraw[1];
            #pragma unroll
            for (int e = 0; e < 8; e++) { psum[0] += __half2float(h0[e]); psum[1] += __half2float(h1[e]); }
            *(uint4*)&Es[nxt][re][ce]      = eraw[0];
            *(uint4*)&Es[nxt][64 + re][ce] = eraw[1];
            __half v0[4], v1[4];
            v0[0]=__float2half_rn(vraw[0].x+bvv4[0]); v0[1]=__float2half_rn(vraw[0].y+bvv4[1]);
            v0[2]=__float2half_rn(vraw[0].z+bvv4[2]); v0[3]=__float2half_rn(vraw[0].w+bvv4[3]);
            v1[0]=__float2half_rn(vraw[1].x+bvv4[0]); v1[1]=__float2half_rn(vraw[1].y+bvv4[1]);
            v1[2]=__float2half_rn(vraw[1].z+bvv4[2]); v1[3]=__float2half_rn(vraw[1].w+bvv4[3]);
            *(uint2*)&Vs[nxt][rv][cv4]      = *(uint2*)v0;
            *(uint2*)&Vs[nxt][16 + rv][cv4] = *(uint2*)v1;
            __syncthreads();
        }
    }

    // row sums -> 1/sum
    __syncthreads();
    rbuf[re][t & 3]      = psum[0];
    rbuf[64 + re][t & 3] = psum[1];
    __syncthreads();
    if (t < 128) {
        float s = rbuf[t][0] + rbuf[t][1] + rbuf[t][2] + rbuf[t][3];
        float inv = 1.0f / s;
        rsinv[t] = inv;
        irs[(size_t)z * S_ + brow + t] = inv;
    }
    __syncthreads();

    // epilogue: reuse Es as per-warp float stage (all MMAs complete)
    float* stgw = (float*)&Es[0][0][0] + w * (16*20);
    int lane = t & 31;
    int r = lane >> 1, c = (lane & 1) * 8;
    #pragma unroll
    for (int i = 0; i < 2; i++)
        #pragma unroll
        for (int j = 0; j < 2; j++) {
            int rl = wm*32 + i*16;
            wmma::store_matrix_sync(stgw, cf[i][j], 20, wmma::mem_row_major);
            __syncwarp();
            float sc = rsinv[rl + r];
            float* gp = Cp + (brow + rl + r) * (size_t)E_ + wn*32 + j*16 + c;
            float4 o0, o1;
            o0.x = stgw[r*20 + c+0]*sc; o0.y = stgw[r*20 + c+1]*sc;
            o0.z = stgw[r*20 + c+2]*sc; o0.w = stgw[r*20 + c+3]*sc;
            o1.x = stgw[r*20 + c+4]*sc; o1.y = stgw[r*20 + c+5]*sc;
            o1.z = stgw[r*20 + c+6]*sc; o1.w = stgw[r*20 + c+7]*sc;
            *(float4*)gp = o0;
            *(float4*)(gp+4) = o1;
            __syncwarp();
        }
}

// ---------------- RoPE cos/sin table (double precision, one-time) ----------------
__global__ void build_rope_table(float* __restrict__ ct, float* __restrict__ st) {
    int idx = blockIdx.x * blockDim.x + threadIdx.x;
    if (idx >= S_ * 32) return;
    int i = idx & 31;
    int s = idx >> 5;
    double expo = ((double)(2*i)) / 64.0;
    double invf = pow(10000.0, -expo);
    double f = (double)s * invf;
    ct[idx] = (float)cos(f);
    st[idx] = (float)sin(f);
}

// -------- RoPE on fp32 Q/K, bias folded, Q pre-scaled by 1/8 --------
__global__ void rope_apply(float* __restrict__ Q, float* __restrict__ K,
                           const float* __restrict__ bq, const float* __restrict__ bk,
                           const float* __restrict__ ct, const float* __restrict__ st) {
    int id = blockIdx.x * blockDim.x + threadIdx.x;
    const int total = NTOK * H_ * 32;            // 4,194,304
    if (id >= 2 * total) return;
    bool isQ = (id < total);
    float* X = isQ ? Q : K;
    const float* bias = isQ ? bq : bk;
    float scl = isQ ? 0.125f : 1.0f;
    int r = isQ ? id : id - total;
    int i    = r & 31;
    int h    = (r >> 5) & 15;
    int trow = r >> 9;
    int s    = trow & (S_ - 1);
    float c  = ct[s*32 + i];
    float sn = st[s*32 + i];
    float b1 = bias[h*D_ + i];
    float b2 = bias[h*D_ + i + 32];
    float* p = X + (size_t)trow * E_ + h * D_ + i;
    float x1 = p[0] + b1, x2 = p[32] + b2;
    p[0]  = (x1 * c - x2 * sn) * scl;
    p[32] = (x2 * c + x1 * sn) * scl;
}

// ---------------- attn_avg = mean over heads of E*irs ----------------
__global__ void avg_heads(const __half* __restrict__ Eg, const float* __restrict__ irs,
                          float* __restrict__ out) {
    size_t i = (size_t)blockIdx.x * blockDim.x + threadIdx.x;    // 8-elem group
    const size_t TOT = (size_t)B_ * S_ * (S_/8);
    if (i >= TOT) return;
    size_t k8 = i % (S_/8);
    size_t q  = (i / (S_/8)) % S_;
    size_t b  = i / ((size_t)(S_/8) * S_);
    float acc[8] = {0,0,0,0,0,0,0,0};
    #pragma unroll
    for (int h = 0; h < H_; h++) {
        size_t zh = b * H_ + h;
        uint4 raw = *(const uint4*)(Eg + (zh * S_ + q) * (size_t)S_ + k8*8);
        const __half* hp = (const __half*)&raw;
        float inv = irs[zh * S_ + q];
        #pragma unroll
        for (int e = 0; e < 8; e++)
            acc[e] += __half2float(hp[e]) * inv;
    }
    float* op = out + (b * S_ + q) * (size_t)S_ + k8*8;
    #pragma unroll
    for (int e = 0; e < 8; e++) op[e] = acc[e] * (1.0f/16.0f);
}

// ---------------- out += bo ----------------
__global__ void add_bias(float* __restrict__ out, const float* __restrict__ bo) {
    size_t i = (size_t)blockIdx.x * blockDim.x + threadIdx.x;
    if (i >= (size_t)NTOK * E_ / 4) return;
    int col = (int)((i << 2) & (E_ - 1));
    float4 v = ((float4*)out)[i];
    const float4 bb = *(const float4*)(bo + col);
    v.x += bb.x; v.y += bb.y; v.z += bb.z; v.w += bb.w;
    ((float4*)out)[i] = v;
}

// ---------------- launch ----------------
extern "C" void kernel_launch(void* const* d_in, const int* in_sizes, int n_in,
                              void* d_out, int out_size)
{
    const float* query = (const float*)d_in[0];
    const float* key   = (const float*)d_in[1];
    const float* value = (const float*)d_in[2];
    const float* Wq = (const float*)d_in[3];
    const float* bq = (const float*)d_in[4];
    const float* Wk = (const float*)d_in[5];
    const float* bk = (const float*)d_in[6];
    const float* Wv = (const float*)d_in[7];
    const float* bv = (const float*)d_in[8];
    const float* Wo = (const float*)d_in[9];
    const float* bo = (const float*)d_in[10];

    float* out      = (float*)d_out;
    float* attn_avg = out + (size_t)NTOK * E_;

    __half *Eh;
    float *Qp, *Kp, *Vp, *AOp, *irs, *ctp, *stp;
    cudaGetSymbolAddress((void**)&Qp,  d_Q);
    cudaGetSymbolAddress((void**)&Kp,  d_K);
    cudaGetSymbolAddress((void**)&Vp,  d_V);
    cudaGetSymbolAddress((void**)&Eh,  d_E);
    cudaGetSymbolAddress((void**)&AOp, d_AO);
    cudaGetSymbolAddress((void**)&irs, d_irs);
    cudaGetSymbolAddress((void**)&ctp, d_ct);
    cudaGetSymbolAddress((void**)&stp, d_st);

    build_rope_table<<<(S_*32)/256, 256>>>(ctp, stp);

    // QKV projections: fp32 in/out, fp16 MMA inside, pipelined
    dim3 g1(E_/128, NTOK/128, 1);
    hgemm_proj<<<g1, 256>>>(query, Wq, Qp, E_, E_, E_, E_);
    hgemm_proj<<<g1, 256>>>(key,   Wk, Kp, E_, E_, E_, E_);
    hgemm_proj<<<g1, 256>>>(value, Wv, Vp, E_, E_, E_, E_);

    // RoPE (+bias, +1/8 on Q), fp32 in place
    rope_apply<<<(2 * NTOK * H_ * 32) / 256, 256>>>(Qp, Kp, bq, bk, ctp, stp);

    // E = exp(scores), fp16 out
    dim3 g3(S_/128, S_/128, B_*H_);
    hgemm_scores<<<g3, 256>>>(Qp, Kp, Eh);

    // AO = (E @ (V+bv)) / rowsum, fp32, pipelined
    dim3 g5(S_/128, 1, B_*H_);
    hgemm_pv<<<g5, 256>>>(Eh, Vp, bv, AOp, irs);

    // Output projection + bias
    hgemm_proj<<<g1, 256>>>(AOp, Wo, out, E_, E_, E_, E_);
    add_bias<<<(NTOK*E_/4 + 255)/256, 256>>>(out, bo);

    // attn_avg from E + inverse row sums
    avg_heads<<<(B_*S_*(S_/8) + 255)/256, 256>>>(Eh, irs, attn_avg);
}

// round 13
// speedup vs baseline: 3.9265x; 1.0262x over previous
#include <cuda_runtime.h>
#include <cuda_fp16.h>
#include <mma.h>
#include <math.h>
#include <cstdint>

using namespace nvcuda;

#define B_ 4
#define S_ 2048
#define E_ 1024
#define H_ 16
#define D_ 64
#define NTOK (B_*S_)   // 8192

// ---------------- scratch (__device__ globals) ----------------
__device__ __half d_qh[(size_t)NTOK*E_];       // fp16 raw inputs
__device__ __half d_kh[(size_t)NTOK*E_];
__device__ __half d_vh[(size_t)NTOK*E_];
__device__ __half d_Wqh[(size_t)E_*E_];
__device__ __half d_Wkh[(size_t)E_*E_];
__device__ __half d_Wvh[(size_t)E_*E_];
__device__ __half d_Woh[(size_t)E_*E_];
__device__ float  d_Q[(size_t)NTOK*E_];        // fp32 proj outputs (pre-rope)
__device__ float  d_K[(size_t)NTOK*E_];
__device__ float  d_V[(size_t)NTOK*E_];
__device__ __half d_Qr[(size_t)NTOK*E_];       // fp16 rope outputs
__device__ __half d_Kr[(size_t)NTOK*E_];
__device__ __half d_Vb[(size_t)NTOK*E_];       // fp16 V+bias
__device__ __half d_AOh[(size_t)NTOK*E_];      // fp16 attention output
__device__ __half d_E[(size_t)B_*H_*S_*S_];    // 536 MB: exp(scores)
__device__ float  d_irs[(size_t)B_*H_*S_];     // 1/rowsum
__device__ float  d_ct[S_*32];
__device__ float  d_st[S_*32];

// ---------------- cp.async helpers ----------------
__device__ __forceinline__ void cp16(void* s, const void* g) {
    unsigned sa = (unsigned)__cvta_generic_to_shared(s);
    asm volatile("cp.async.ca.shared.global [%0], [%1], 16;\n" :: "r"(sa), "l"(g));
}
__device__ __forceinline__ void cp_commit() { asm volatile("cp.async.commit_group;\n"); }
__device__ __forceinline__ void cp_wait0()  { asm volatile("cp.async.wait_group 0;\n"); }
__device__ __forceinline__ void cp_wait1()  { asm volatile("cp.async.wait_group 1;\n"); }

// ---------------- FMA-only exp (B300 MUFU is slow: rt_SMSP=8) ----------------
__device__ __forceinline__ float fast_exp(float x) {
    float t  = x * 1.44269504088896341f;
    t = fmaxf(fminf(t, 126.0f), -126.0f);
    float fn = rintf(t);
    int   n  = (int)fn;
    float f  = t - fn;
    float g  = f * 0.69314718055994531f;
    float p  = 1.0f + g*(1.0f + g*(0.5f + g*(0.16666666667f + g*(0.04166666667f + g*0.008333333333f))));
    return __int_as_float((n + 127) << 23) * p;
}

// ---------------- fp32 -> fp16 conversion (single rounding, one-shot) ----------------
__global__ void cvt_h(const float* __restrict__ x, __half* __restrict__ y, int n8) {
    int i = blockIdx.x * blockDim.x + threadIdx.x;
    if (i >= n8) return;
    const float4* xp = (const float4*)(x) + i*2;
    float4 a = xp[0], b = xp[1];
    __half h[8];
    h[0]=__float2half_rn(a.x); h[1]=__float2half_rn(a.y);
    h[2]=__float2half_rn(a.z); h[3]=__float2half_rn(a.w);
    h[4]=__float2half_rn(b.x); h[5]=__float2half_rn(b.y);
    h[6]=__float2half_rn(b.z); h[7]=__float2half_rn(b.w);
    ((uint4*)y)[i] = *(uint4*)h;
}

// ============ pure-fp16 NT GEMM, cp.async 2-stage: C_fp32 = A * B^T ============
// 128x128 tile, BK=32, 8 warps (2x4), warp 64x32, m16n16k16.
__global__ void __launch_bounds__(256,2) hgemm16(
    const __half* __restrict__ A, const __half* __restrict__ B,
    float* __restrict__ C, int K, int lda, int ldb, int ldc)
{
    __shared__ __half As[2][128][40];
    __shared__ __half Bs[2][128][40];

    int t = threadIdx.x;
    int w = t >> 5;
    int wm = w >> 2, wn = w & 3;
    size_t brow = (size_t)blockIdx.y * 128;
    size_t bcol = (size_t)blockIdx.x * 128;
    int lr = t >> 2, lc8 = (t & 3) << 3;

    wmma::fragment<wmma::accumulator,16,16,16,float> cf[4][2];
    #pragma unroll
    for (int i = 0; i < 4; i++)
        #pragma unroll
        for (int j = 0; j < 2; j++) wmma::fill_fragment(cf[i][j], 0.0f);

    // prologue: stage 0
    #pragma unroll
    for (int u = 0; u < 2; u++) {
        int r = u*64 + lr;
        cp16(&As[0][r][lc8], A + (brow + r) * (size_t)lda + lc8);
        cp16(&Bs[0][r][lc8], B + (bcol + r) * (size_t)ldb + lc8);
    }
    cp_commit();

    int nit = K >> 5;
    for (int it = 0; it < nit; it++) {
        int cur = it & 1;
        if (it + 1 < nit) {
            int k0 = (it + 1) << 5, nxt = 1 - cur;
            #pragma unroll
            for (int u = 0; u < 2; u++) {
                int r = u*64 + lr;
                cp16(&As[nxt][r][lc8], A + (brow + r) * (size_t)lda + k0 + lc8);
                cp16(&Bs[nxt][r][lc8], B + (bcol + r) * (size_t)ldb + k0 + lc8);
            }
            cp_commit();
            cp_wait1();
        } else {
            cp_wait0();
        }
        __syncthreads();
        #pragma unroll
        for (int kk = 0; kk < 32; kk += 16) {
            wmma::fragment<wmma::matrix_a,16,16,16,__half,wmma::row_major> af[4];
            wmma::fragment<wmma::matrix_b,16,16,16,__half,wmma::col_major> bf[2];
            #pragma unroll
            for (int i = 0; i < 4; i++) wmma::load_matrix_sync(af[i], &As[cur][wm*64 + i*16][kk], 40);
            #pragma unroll
            for (int j = 0; j < 2; j++) wmma::load_matrix_sync(bf[j], &Bs[cur][wn*32 + j*16][kk], 40);
            #pragma unroll
            for (int i = 0; i < 4; i++)
                #pragma unroll
                for (int j = 0; j < 2; j++)
                    wmma::mma_sync(cf[i][j], af[i], bf[j], cf[i][j]);
        }
        __syncthreads();
    }

    #pragma unroll
    for (int i = 0; i < 4; i++)
        #pragma unroll
        for (int j = 0; j < 2; j++) {
            size_t row = brow + wm*64 + i*16;
            size_t col = bcol + wn*32 + j*16;
            wmma::store_matrix_sync(C + row * (size_t)ldc + col, cf[i][j], ldc, wmma::mem_row_major);
        }
}

// ============ Scores+exp: E[b,h] = exp(Q_h @ K_h^T) — fp16 in/out, K=64 ============
__global__ void __launch_bounds__(256,2) hgemm_scores(
    const __half* __restrict__ Q, const __half* __restrict__ Kf,
    __half* __restrict__ Eg)
{
    __shared__ __half As[128][72];
    __shared__ __half Bs[128][72];
    __shared__ float  stg[8][16][20];

    int z = blockIdx.z, b = z >> 4, h = z & 15;
    const __half* Ap = Q  + (size_t)b * S_ * E_ + h * D_;
    const __half* Bp = Kf + (size_t)b * S_ * E_ + h * D_;
    __half* Cp = Eg + (size_t)z * S_ * S_;

    int t = threadIdx.x;
    int w = t >> 5;
    int wm = w >> 2, wn = w & 3;
    size_t brow = (size_t)blockIdx.y * 128;
    size_t bcol = (size_t)blockIdx.x * 128;

    #pragma unroll
    for (int u = 0; u < 4; u++) {
        int i = u*256 + t;
        int r = i >> 3, c8 = (i & 7) << 3;
        *(uint4*)&As[r][c8] = *(const uint4*)(Ap + (brow + r) * (size_t)E_ + c8);
        *(uint4*)&Bs[r][c8] = *(const uint4*)(Bp + (bcol + r) * (size_t)E_ + c8);
    }
    __syncthreads();

    wmma::fragment<wmma::accumulator,16,16,16,float> cf[4][2];
    #pragma unroll
    for (int i = 0; i < 4; i++)
        #pragma unroll
        for (int j = 0; j < 2; j++) wmma::fill_fragment(cf[i][j], 0.0f);

    #pragma unroll
    for (int kk = 0; kk < 64; kk += 16) {
        wmma::fragment<wmma::matrix_a,16,16,16,__half,wmma::row_major> af[4];
        wmma::fragment<wmma::matrix_b,16,16,16,__half,wmma::col_major> bf[2];
        #pragma unroll
        for (int i = 0; i < 4; i++) wmma::load_matrix_sync(af[i], &As[wm*64 + i*16][kk], 72);
        #pragma unroll
        for (int j = 0; j < 2; j++) wmma::load_matrix_sync(bf[j], &Bs[wn*32 + j*16][kk], 72);
        #pragma unroll
        for (int i = 0; i < 4; i++)
            #pragma unroll
            for (int j = 0; j < 2; j++)
                wmma::mma_sync(cf[i][j], af[i], bf[j], cf[i][j]);
    }

    int lane = t & 31;
    int r = lane >> 1, c = (lane & 1) * 8;
    #pragma unroll
    for (int i = 0; i < 4; i++)
        #pragma unroll
        for (int j = 0; j < 2; j++) {
            size_t row = brow + wm*64 + i*16;
            size_t col = bcol + wn*32 + j*16;
            wmma::store_matrix_sync(&stg[w][0][0], cf[i][j], 20, wmma::mem_row_major);
            __syncwarp();
            __half hh[8];
            #pragma unroll
            for (int e = 0; e < 8; e++) {
                float s = fminf(fmaxf(stg[w][r][c+e], -20.0f), 8.0f);
                hh[e] = __float2half_rn(fast_exp(s));
            }
            *(uint4*)(Cp + (row + r) * (size_t)S_ + col + c) = *(uint4*)hh;
            __syncwarp();
        }
}

// ============ PV: AOh = h((E @ Vb) / rowsum(E)); all-fp16, 2-stage pipelined ============
__global__ void __launch_bounds__(256,2) hgemm_pv(
    const __half* __restrict__ Eg, const __half* __restrict__ Vb,
    __half* __restrict__ AO, float* __restrict__ irs)
{
    __shared__ __half Es[2][128][40];
    __shared__ __half Vs[2][32][72];
    __shared__ float  rbuf[128][4];
    __shared__ float  rsinv[128];

    int z = blockIdx.z, b = z >> 4, h = z & 15;
    const __half* Ep = Eg + (size_t)z * S_ * S_;
    const __half* Vp = Vb + (size_t)b * S_ * E_ + h * D_;
    __half* Cp = AO + (size_t)b * S_ * E_ + h * D_;
    size_t brow = (size_t)blockIdx.x * 128;

    int t = threadIdx.x;
    int w = t >> 5;
    int wm = w >> 1, wn = w & 1;          // 4 x 2 warps, warp 32x32
    int re = t >> 2, ce = (t & 3) << 3;   // E loader: rows re, re+64
    int rv = t >> 3, cv8 = (t & 7) << 3;  // V loader: 32 rows x 8 uint4

    float psum[2] = {0.f, 0.f};
    wmma::fragment<wmma::accumulator,16,16,16,float> cf[2][2];
    #pragma unroll
    for (int i = 0; i < 2; i++)
        #pragma unroll
        for (int j = 0; j < 2; j++) wmma::fill_fragment(cf[i][j], 0.0f);

    uint4 eraw[2];

    // prologue: tile 0
    eraw[0] = *(const uint4*)(Ep + (brow + re)      * (size_t)S_ + ce);
    eraw[1] = *(const uint4*)(Ep + (brow + 64 + re) * (size_t)S_ + ce);
    cp16(&Vs[0][rv][cv8], Vp + (size_t)rv * E_ + cv8);
    cp_commit();
    {
        const __half* h0 = (const __half*)&eraw[0];
        const __half* h1 = (const __half*)&eraw[1];
        #pragma unroll
        for (int e = 0; e < 8; e++) { psum[0] += __half2float(h0[e]); psum[1] += __half2float(h1[e]); }
        *(uint4*)&Es[0][re][ce]      = eraw[0];
        *(uint4*)&Es[0][64 + re][ce] = eraw[1];
    }
    cp_wait0();
    __syncthreads();

    const int NIT = S_ >> 5;   // 64
    for (int it = 0; it < NIT; it++) {
        int cur = it & 1;
        if (it + 1 < NIT) {
            int k0 = (it + 1) << 5, nxt = 1 - cur;
            eraw[0] = *(const uint4*)(Ep + (brow + re)      * (size_t)S_ + k0 + ce);
            eraw[1] = *(const uint4*)(Ep + (brow + 64 + re) * (size_t)S_ + k0 + ce);
            cp16(&Vs[nxt][rv][cv8], Vp + (size_t)(k0 + rv) * E_ + cv8);
            cp_commit();
            const __half* h0 = (const __half*)&eraw[0];
            const __half* h1 = (const __half*)&eraw[1];
            #pragma unroll
            for (int e = 0; e < 8; e++) { psum[0] += __half2float(h0[e]); psum[1] += __half2float(h1[e]); }
            *(uint4*)&Es[nxt][re][ce]      = eraw[0];
            *(uint4*)&Es[nxt][64 + re][ce] = eraw[1];
        }
        #pragma unroll
        for (int kk = 0; kk < 32; kk += 16) {
            wmma::fragment<wmma::matrix_a,16,16,16,__half,wmma::row_major> af[2];
            wmma::fragment<wmma::matrix_b,16,16,16,__half,wmma::row_major> bf[2];
            #pragma unroll
            for (int i = 0; i < 2; i++) wmma::load_matrix_sync(af[i], &Es[cur][wm*32 + i*16][kk], 40);
            #pragma unroll
            for (int j = 0; j < 2; j++) wmma::load_matrix_sync(bf[j], &Vs[cur][kk][wn*32 + j*16], 72);
            #pragma unroll
            for (int i = 0; i < 2; i++)
                #pragma unroll
                for (int j = 0; j < 2; j++)
                    wmma::mma_sync(cf[i][j], af[i], bf[j], cf[i][j]);
        }
        if (it + 1 < NIT) { cp_wait0(); }
        __syncthreads();
    }

    // row sums -> 1/sum
    rbuf[re][t & 3]      = psum[0];
    rbuf[64 + re][t & 3] = psum[1];
    __syncthreads();
    if (t < 128) {
        float s = rbuf[t][0] + rbuf[t][1] + rbuf[t][2] + rbuf[t][3];
        float inv = 1.0f / s;
        rsinv[t] = inv;
        irs[(size_t)z * S_ + brow + t] = inv;
    }
    __syncthreads();

    // epilogue: reuse Es as per-warp float stage, write fp16 (single rounding)
    float* stgw = (float*)&Es[0][0][0] + w * (16*20);
    int lane = t & 31;
    int r = lane >> 1, c = (lane & 1) * 8;
    #pragma unroll
    for (int i = 0; i < 2; i++)
        #pragma unroll
        for (int j = 0; j < 2; j++) {
            int rl = wm*32 + i*16;
            wmma::store_matrix_sync(stgw, cf[i][j], 20, wmma::mem_row_major);
            __syncwarp();
            float sc = rsinv[rl + r];
            __half hh[8];
            #pragma unroll
            for (int e = 0; e < 8; e++) hh[e] = __float2half_rn(stgw[r*20 + c + e] * sc);
            *(uint4*)(Cp + (brow + rl + r) * (size_t)E_ + wn*32 + j*16 + c) = *(uint4*)hh;
            __syncwarp();
        }
}

// ---------------- RoPE cos/sin table (double precision, one-time) ----------------
__global__ void build_rope_table(float* __restrict__ ct, float* __restrict__ st) {
    int idx = blockIdx.x * blockDim.x + threadIdx.x;
    if (idx >= S_ * 32) return;
    int i = idx & 31;
    int s = idx >> 5;
    double expo = ((double)(2*i)) / 64.0;
    double invf = pow(10000.0, -expo);
    double f = (double)s * invf;
    ct[idx] = (float)cos(f);
    st[idx] = (float)sin(f);
}

// -------- RoPE: fp32 in, fp16 out; bias folded, Q pre-scaled by 1/8 --------
__global__ void rope16(const float* __restrict__ Q, const float* __restrict__ K,
                       __half* __restrict__ Qo, __half* __restrict__ Ko,
                       const float* __restrict__ bq, const float* __restrict__ bk,
                       const float* __restrict__ ct, const float* __restrict__ st) {
    int id = blockIdx.x * blockDim.x + threadIdx.x;
    const int total = NTOK * H_ * 16;            // half2 pairs
    if (id >= 2 * total) return;
    bool isQ = (id < total);
    int r = isQ ? id : id - total;
    int i2   = r & 15;
    int h    = (r >> 4) & 15;
    int trow = r >> 8;
    int s    = trow & (S_ - 1);
    int ci   = s*32 + i2*2;
    float c0 = ct[ci], c1 = ct[ci+1];
    float s0 = st[ci], s1 = st[ci+1];
    const float* bias = isQ ? bq : bk;
    const float* X = isQ ? Q : K;
    __half* Xo = isQ ? Qo : Ko;
    float scl = isQ ? 0.125f : 1.0f;
    int bc = h*D_ + i2*2;
    size_t base = (size_t)trow * E_ + bc;
    float x1a = X[base]      + bias[bc];
    float x1b = X[base+1]    + bias[bc+1];
    float x2a = X[base+32]   + bias[bc+32];
    float x2b = X[base+33]   + bias[bc+33];
    *(__half2*)(Xo + base)      = __floats2half2_rn((x1a*c0 - x2a*s0)*scl, (x1b*c1 - x2b*s1)*scl);
    *(__half2*)(Xo + base + 32) = __floats2half2_rn((x2a*c0 + x1a*s0)*scl, (x2b*c1 + x1b*s1)*scl);
}

// ---------------- Vb = h(V + bv) (single rounding) ----------------
__global__ void vbias(const float* __restrict__ V, const float* __restrict__ bv,
                      __half* __restrict__ Vb) {
    size_t i = (size_t)blockIdx.x * blockDim.x + threadIdx.x;   // 8-elem group
    if (i >= (size_t)NTOK * E_ / 8) return;
    int col = (int)((i << 3) & (E_ - 1));
    const float4* vp = (const float4*)V + i*2;
    float4 a = vp[0], b = vp[1];
    const float4 b0 = *(const float4*)(bv + col);
    const float4 b1 = *(const float4*)(bv + col + 4);
    __half h[8];
    h[0]=__float2half_rn(a.x+b0.x); h[1]=__float2half_rn(a.y+b0.y);
    h[2]=__float2half_rn(a.z+b0.z); h[3]=__float2half_rn(a.w+b0.w);
    h[4]=__float2half_rn(b.x+b1.x); h[5]=__float2half_rn(b.y+b1.y);
    h[6]=__float2half_rn(b.z+b1.z); h[7]=__float2half_rn(b.w+b1.w);
    ((uint4*)Vb)[i] = *(uint4*)h;
}

// ---------------- attn_avg = mean over heads of E*irs ----------------
__global__ void avg_heads(const __half* __restrict__ Eg, const float* __restrict__ irs,
                          float* __restrict__ out) {
    size_t i = (size_t)blockIdx.x * blockDim.x + threadIdx.x;    // 8-elem group
    const size_t TOT = (size_t)B_ * S_ * (S_/8);
    if (i >= TOT) return;
    size_t k8 = i % (S_/8);
    size_t q  = (i / (S_/8)) % S_;
    size_t b  = i / ((size_t)(S_/8) * S_);
    float acc[8] = {0,0,0,0,0,0,0,0};
    #pragma unroll
    for (int h = 0; h < H_; h++) {
        size_t zh = b * H_ + h;
        uint4 raw = *(const uint4*)(Eg + (zh * S_ + q) * (size_t)S_ + k8*8);
        const __half* hp = (const __half*)&raw;
        float inv = irs[zh * S_ + q];
        #pragma unroll
        for (int e = 0; e < 8; e++)
            acc[e] += __half2float(hp[e]) * inv;
    }
    float* op = out + (b * S_ + q) * (size_t)S_ + k8*8;
    #pragma unroll
    for (int e = 0; e < 8; e++) op[e] = acc[e] * (1.0f/16.0f);
}

// ---------------- out += bo ----------------
__global__ void add_bias(float* __restrict__ out, const float* __restrict__ bo) {
    size_t i = (size_t)blockIdx.x * blockDim.x + threadIdx.x;
    if (i >= (size_t)NTOK * E_ / 4) return;
    int col = (int)((i << 2) & (E_ - 1));
    float4 v = ((float4*)out)[i];
    const float4 bb = *(const float4*)(bo + col);
    v.x += bb.x; v.y += bb.y; v.z += bb.z; v.w += bb.w;
    ((float4*)out)[i] = v;
}

// ---------------- launch ----------------
extern "C" void kernel_launch(void* const* d_in, const int* in_sizes, int n_in,
                              void* d_out, int out_size)
{
    const float* query = (const float*)d_in[0];
    const float* key   = (const float*)d_in[1];
    const float* value = (const float*)d_in[2];
    const float* Wq = (const float*)d_in[3];
    const float* bq = (const float*)d_in[4];
    const float* Wk = (const float*)d_in[5];
    const float* bk = (const float*)d_in[6];
    const float* Wv = (const float*)d_in[7];
    const float* bv = (const float*)d_in[8];
    const float* Wo = (const float*)d_in[9];
    const float* bo = (const float*)d_in[10];

    float* out      = (float*)d_out;
    float* attn_avg = out + (size_t)NTOK * E_;

    __half *qh,*kh,*vh,*Wqh,*Wkh,*Wvh,*Woh,*Qr,*Kr,*Vbp,*AOh,*Eh;
    float *Qp,*Kp,*Vp,*irs,*ctp,*stp;
    cudaGetSymbolAddress((void**)&qh,  d_qh);
    cudaGetSymbolAddress((void**)&kh,  d_kh);
    cudaGetSymbolAddress((void**)&vh,  d_vh);
    cudaGetSymbolAddress((void**)&Wqh, d_Wqh);
    cudaGetSymbolAddress((void**)&Wkh, d_Wkh);
    cudaGetSymbolAddress((void**)&Wvh, d_Wvh);
    cudaGetSymbolAddress((void**)&Woh, d_Woh);
    cudaGetSymbolAddress((void**)&Qp,  d_Q);
    cudaGetSymbolAddress((void**)&Kp,  d_K);
    cudaGetSymbolAddress((void**)&Vp,  d_V);
    cudaGetSymbolAddress((void**)&Qr,  d_Qr);
    cudaGetSymbolAddress((void**)&Kr,  d_Kr);
    cudaGetSymbolAddress((void**)&Vbp, d_Vb);
    cudaGetSymbolAddress((void**)&AOh, d_AOh);
    cudaGetSymbolAddress((void**)&Eh,  d_E);
    cudaGetSymbolAddress((void**)&irs, d_irs);
    cudaGetSymbolAddress((void**)&ctp, d_ct);
    cudaGetSymbolAddress((void**)&stp, d_st);

    build_rope_table<<<(S_*32)/256, 256>>>(ctp, stp);

    // fp32 -> fp16 conversions (single rounding each; numerics unchanged)
    const int NTE8 = NTOK*E_/8, EE8 = E_*E_/8;
    cvt_h<<<(NTE8+255)/256, 256>>>(query, qh, NTE8);
    cvt_h<<<(NTE8+255)/256, 256>>>(key,   kh, NTE8);
    cvt_h<<<(NTE8+255)/256, 256>>>(value, vh, NTE8);
    cvt_h<<<(EE8+255)/256, 256>>>(Wq, Wqh, EE8);
    cvt_h<<<(EE8+255)/256, 256>>>(Wk, Wkh, EE8);
    cvt_h<<<(EE8+255)/256, 256>>>(Wv, Wvh, EE8);
    cvt_h<<<(EE8+255)/256, 256>>>(Wo, Woh, EE8);

    // QKV projections: fp16 in, fp32 out
    dim3 g1(E_/128, NTOK/128, 1);
    hgemm16<<<g1, 256>>>(qh, Wqh, Qp, E_, E_, E_, E_);
    hgemm16<<<g1, 256>>>(kh, Wkh, Kp, E_, E_, E_, E_);
    hgemm16<<<g1, 256>>>(vh, Wvh, Vp, E_, E_, E_, E_);

    // RoPE (+bias, +1/8 on Q): fp32 -> fp16
    rope16<<<(2 * NTOK * H_ * 16) / 256, 256>>>(Qp, Kp, Qr, Kr, bq, bk, ctp, stp);

    // Vb = h(V + bv)
    vbias<<<(NTOK*E_/8 + 255)/256, 256>>>(Vp, bv, Vbp);

    // E = exp(scores), fp16
    dim3 g3(S_/128, S_/128, B_*H_);
    hgemm_scores<<<g3, 256>>>(Qr, Kr, Eh);

    // AOh = h((E @ Vb)/rowsum), fp16
    dim3 g5(S_/128, 1, B_*H_);
    hgemm_pv<<<g5, 256>>>(Eh, Vbp, AOh, irs);

    // Output projection (fp16 in, fp32 out) + bias
    hgemm16<<<g1, 256>>>(AOh, Woh, out, E_, E_, E_, E_);
    add_bias<<<(NTOK*E_/4 + 255)/256, 256>>>(out, bo);

    // attn_avg from E + inverse row sums
    avg_heads<<<(B_*S_*(S_/8) + 255)/256, 256>>>(Eh, irs, attn_avg);
}

// round 14
// speedup vs baseline: 4.1899x; 1.0671x over previous
#include <cuda_runtime.h>
#include <cuda_fp16.h>
#include <mma.h>
#include <math.h>
#include <cstdint>

using namespace nvcuda;

#define B_ 4
#define S_ 2048
#define E_ 1024
#define H_ 16
#define D_ 64
#define NTOK (B_*S_)   // 8192

// ---------------- scratch (__device__ globals) ----------------
__device__ __half d_qh[(size_t)NTOK*E_];       // fp16 raw inputs
__device__ __half d_kh[(size_t)NTOK*E_];
__device__ __half d_vh[(size_t)NTOK*E_];
__device__ __half d_Wqh[(size_t)E_*E_];
__device__ __half d_Wkh[(size_t)E_*E_];
__device__ __half d_Wvh[(size_t)E_*E_];
__device__ __half d_Woh[(size_t)E_*E_];
__device__ float  d_Q[(size_t)NTOK*E_];        // fp32 proj outputs (pre-rope)
__device__ float  d_K[(size_t)NTOK*E_];
__device__ float  d_V[(size_t)NTOK*E_];
__device__ __half d_Qr[(size_t)NTOK*E_];       // fp16 rope outputs
__device__ __half d_Kr[(size_t)NTOK*E_];
__device__ __half d_Vb[(size_t)NTOK*E_];       // fp16 V+bias
__device__ __half d_AOh[(size_t)NTOK*E_];      // fp16 attention output
__device__ __half d_E[(size_t)B_*H_*S_*S_];    // 536 MB: exp(scores)
__device__ float  d_rs[(size_t)B_*H_*S_];      // rowsum (atomic accum)
__device__ float  d_irs[(size_t)B_*H_*S_];     // 1/rowsum
__device__ float  d_ct[S_*32];
__device__ float  d_st[S_*32];

// ---------------- cp.async helpers ----------------
__device__ __forceinline__ void cp16(void* s, const void* g) {
    unsigned sa = (unsigned)__cvta_generic_to_shared(s);
    asm volatile("cp.async.ca.shared.global [%0], [%1], 16;\n" :: "r"(sa), "l"(g));
}
__device__ __forceinline__ void cp_commit() { asm volatile("cp.async.commit_group;\n"); }
__device__ __forceinline__ void cp_wait0()  { asm volatile("cp.async.wait_group 0;\n"); }

// ---------------- FMA-only exp (B300 MUFU is slow: rt_SMSP=8) ----------------
__device__ __forceinline__ float fast_exp(float x) {
    float t  = x * 1.44269504088896341f;
    t = fmaxf(fminf(t, 126.0f), -126.0f);
    float fn = rintf(t);
    int   n  = (int)fn;
    float f  = t - fn;
    float g  = f * 0.69314718055994531f;
    float p  = 1.0f + g*(1.0f + g*(0.5f + g*(0.16666666667f + g*(0.04166666667f + g*0.008333333333f))));
    return __int_as_float((n + 127) << 23) * p;
}

// ---------------- fp32 -> fp16 conversion (single rounding, one-shot) ----------------
__global__ void cvt_h(const float* __restrict__ x, __half* __restrict__ y, int n8) {
    int i = blockIdx.x * blockDim.x + threadIdx.x;
    if (i >= n8) return;
    const float4* xp = (const float4*)(x) + i*2;
    float4 a = xp[0], b = xp[1];
    __half h[8];
    h[0]=__float2half_rn(a.x); h[1]=__float2half_rn(a.y);
    h[2]=__float2half_rn(a.z); h[3]=__float2half_rn(a.w);
    h[4]=__float2half_rn(b.x); h[5]=__float2half_rn(b.y);
    h[6]=__float2half_rn(b.z); h[7]=__float2half_rn(b.w);
    ((uint4*)y)[i] = *(uint4*)h;
}

// ---------------- rs = 0, irs = 1/rs ----------------
__global__ void rs_zero(float* __restrict__ rs, int n) {
    int i = blockIdx.x * blockDim.x + threadIdx.x;
    if (i < n) rs[i] = 0.0f;
}
__global__ void rs_inv(const float* __restrict__ rs, float* __restrict__ irs, int n) {
    int i = blockIdx.x * blockDim.x + threadIdx.x;
    if (i < n) irs[i] = 1.0f / rs[i];
}

// ============ pure-fp16 NT GEMM, cp.async 2-stage single-sync: C_fp32 = A * B^T ============
// 128x128 tile, BK=32, 8 warps (2x4), warp 64x32, m16n16k16.
__global__ void __launch_bounds__(256,2) hgemm16(
    const __half* __restrict__ A, const __half* __restrict__ B,
    float* __restrict__ C, int K, int lda, int ldb, int ldc)
{
    __shared__ __half As[2][128][40];
    __shared__ __half Bs[2][128][40];

    int t = threadIdx.x;
    int w = t >> 5;
    int wm = w >> 2, wn = w & 3;
    size_t brow = (size_t)blockIdx.y * 128;
    size_t bcol = (size_t)blockIdx.x * 128;
    int lr = t >> 2, lc8 = (t & 3) << 3;

    wmma::fragment<wmma::accumulator,16,16,16,float> cf[4][2];
    #pragma unroll
    for (int i = 0; i < 4; i++)
        #pragma unroll
        for (int j = 0; j < 2; j++) wmma::fill_fragment(cf[i][j], 0.0f);

    // prologue: stage 0
    #pragma unroll
    for (int u = 0; u < 2; u++) {
        int r = u*64 + lr;
        cp16(&As[0][r][lc8], A + (brow + r) * (size_t)lda + lc8);
        cp16(&Bs[0][r][lc8], B + (bcol + r) * (size_t)ldb + lc8);
    }
    cp_commit();

    int nit = K >> 5;
    for (int it = 0; it < nit; it++) {
        int cur = it & 1;
        cp_wait0();
        __syncthreads();          // cur data visible; all warps done reading 1-cur
        if (it + 1 < nit) {
            int k0 = (it + 1) << 5, nxt = 1 - cur;
            #pragma unroll
            for (int u = 0; u < 2; u++) {
                int r = u*64 + lr;
                cp16(&As[nxt][r][lc8], A + (brow + r) * (size_t)lda + k0 + lc8);
                cp16(&Bs[nxt][r][lc8], B + (bcol + r) * (size_t)ldb + k0 + lc8);
            }
            cp_commit();
        }
        #pragma unroll
        for (int kk = 0; kk < 32; kk += 16) {
            wmma::fragment<wmma::matrix_a,16,16,16,__half,wmma::row_major> af[4];
            wmma::fragment<wmma::matrix_b,16,16,16,__half,wmma::col_major> bf[2];
            #pragma unroll
            for (int i = 0; i < 4; i++) wmma::load_matrix_sync(af[i], &As[cur][wm*64 + i*16][kk], 40);
            #pragma unroll
            for (int j = 0; j < 2; j++) wmma::load_matrix_sync(bf[j], &Bs[cur][wn*32 + j*16][kk], 40);
            #pragma unroll
            for (int i = 0; i < 4; i++)
                #pragma unroll
                for (int j = 0; j < 2; j++)
                    wmma::mma_sync(cf[i][j], af[i], bf[j], cf[i][j]);
        }
    }

    #pragma unroll
    for (int i = 0; i < 4; i++)
        #pragma unroll
        for (int j = 0; j < 2; j++) {
            size_t row = brow + wm*64 + i*16;
            size_t col = bcol + wn*32 + j*16;
            wmma::store_matrix_sync(C + row * (size_t)ldc + col, cf[i][j], ldc, wmma::mem_row_major);
        }
}

// ============ Scores+exp: E[b,h] = exp(Q_h @ K_h^T), rowsum via atomicAdd ============
__global__ void __launch_bounds__(256,2) hgemm_scores(
    const __half* __restrict__ Q, const __half* __restrict__ Kf,
    __half* __restrict__ Eg, float* __restrict__ rs)
{
    __shared__ __half As[128][72];
    __shared__ __half Bs[128][72];
    __shared__ float  stg[8][16][20];

    int z = blockIdx.z, b = z >> 4, h = z & 15;
    const __half* Ap = Q  + (size_t)b * S_ * E_ + h * D_;
    const __half* Bp = Kf + (size_t)b * S_ * E_ + h * D_;
    __half* Cp = Eg + (size_t)z * S_ * S_;

    int t = threadIdx.x;
    int w = t >> 5;
    int wm = w >> 2, wn = w & 3;
    size_t brow = (size_t)blockIdx.y * 128;
    size_t bcol = (size_t)blockIdx.x * 128;

    #pragma unroll
    for (int u = 0; u < 4; u++) {
        int i = u*256 + t;
        int r = i >> 3, c8 = (i & 7) << 3;
        *(uint4*)&As[r][c8] = *(const uint4*)(Ap + (brow + r) * (size_t)E_ + c8);
        *(uint4*)&Bs[r][c8] = *(const uint4*)(Bp + (bcol + r) * (size_t)E_ + c8);
    }
    __syncthreads();

    wmma::fragment<wmma::accumulator,16,16,16,float> cf[4][2];
    #pragma unroll
    for (int i = 0; i < 4; i++)
        #pragma unroll
        for (int j = 0; j < 2; j++) wmma::fill_fragment(cf[i][j], 0.0f);

    #pragma unroll
    for (int kk = 0; kk < 64; kk += 16) {
        wmma::fragment<wmma::matrix_a,16,16,16,__half,wmma::row_major> af[4];
        wmma::fragment<wmma::matrix_b,16,16,16,__half,wmma::col_major> bf[2];
        #pragma unroll
        for (int i = 0; i < 4; i++) wmma::load_matrix_sync(af[i], &As[wm*64 + i*16][kk], 72);
        #pragma unroll
        for (int j = 0; j < 2; j++) wmma::load_matrix_sync(bf[j], &Bs[wn*32 + j*16][kk], 72);
        #pragma unroll
        for (int i = 0; i < 4; i++)
            #pragma unroll
            for (int j = 0; j < 2; j++)
                wmma::mma_sync(cf[i][j], af[i], bf[j], cf[i][j]);
    }

    int lane = t & 31;
    int r = lane >> 1, c = (lane & 1) * 8;
    #pragma unroll
    for (int i = 0; i < 4; i++)
        #pragma unroll
        for (int j = 0; j < 2; j++) {
            size_t row = brow + wm*64 + i*16;
            size_t col = bcol + wn*32 + j*16;
            wmma::store_matrix_sync(&stg[w][0][0], cf[i][j], 20, wmma::mem_row_major);
            __syncwarp();
            __half hh[8];
            float psum = 0.0f;
            #pragma unroll
            for (int e = 0; e < 8; e++) {
                float s = fminf(fmaxf(stg[w][r][c+e], -20.0f), 8.0f);
                hh[e] = __float2half_rn(fast_exp(s));
                psum += __half2float(hh[e]);        // sum the SAME stored fp16 values
            }
            *(uint4*)(Cp + (row + r) * (size_t)S_ + col + c) = *(uint4*)hh;
            atomicAdd(&rs[(size_t)z * S_ + row + r], psum);
            __syncwarp();
        }
}

// ============ PV: AOh = h((E @ Vb) * irs); full cp.async, single-sync, no in-loop sums ============
__global__ void __launch_bounds__(256,2) hgemm_pv(
    const __half* __restrict__ Eg, const __half* __restrict__ Vb,
    const float* __restrict__ irs, __half* __restrict__ AO)
{
    __shared__ __half Es[2][128][40];
    __shared__ __half Vs[2][32][72];
    __shared__ float  rsinv[128];

    int z = blockIdx.z, b = z >> 4, h = z & 15;
    const __half* Ep = Eg + (size_t)z * S_ * S_;
    const __half* Vp = Vb + (size_t)b * S_ * E_ + h * D_;
    __half* Cp = AO + (size_t)b * S_ * E_ + h * D_;
    size_t brow = (size_t)blockIdx.x * 128;

    int t = threadIdx.x;
    int w = t >> 5;
    int wm = w >> 1, wn = w & 1;          // 4 x 2 warps, warp 32x32
    int re = t >> 2, ce = (t & 3) << 3;   // E loader: rows re, re+64
    int rv = t >> 3, cv8 = (t & 7) << 3;  // V loader: 32 rows x 8 halves

    wmma::fragment<wmma::accumulator,16,16,16,float> cf[2][2];
    #pragma unroll
    for (int i = 0; i < 2; i++)
        #pragma unroll
        for (int j = 0; j < 2; j++) wmma::fill_fragment(cf[i][j], 0.0f);

    // prologue: stage 0
    cp16(&Es[0][re][ce],      Ep + (brow + re)      * (size_t)S_ + ce);
    cp16(&Es[0][64 + re][ce], Ep + (brow + 64 + re) * (size_t)S_ + ce);
    cp16(&Vs[0][rv][cv8],     Vp + (size_t)rv * E_ + cv8);
    cp_commit();

    const int NIT = S_ >> 5;   // 64
    for (int it = 0; it < NIT; it++) {
        int cur = it & 1;
        cp_wait0();
        __syncthreads();
        if (it + 1 < NIT) {
            int k0 = (it + 1) << 5, nxt = 1 - cur;
            cp16(&Es[nxt][re][ce],      Ep + (brow + re)      * (size_t)S_ + k0 + ce);
            cp16(&Es[nxt][64 + re][ce], Ep + (brow + 64 + re) * (size_t)S_ + k0 + ce);
            cp16(&Vs[nxt][rv][cv8],     Vp + (size_t)(k0 + rv) * E_ + cv8);
            cp_commit();
        }
        #pragma unroll
        for (int kk = 0; kk < 32; kk += 16) {
            wmma::fragment<wmma::matrix_a,16,16,16,__half,wmma::row_major> af[2];
            wmma::fragment<wmma::matrix_b,16,16,16,__half,wmma::row_major> bf[2];
            #pragma unroll
            for (int i = 0; i < 2; i++) wmma::load_matrix_sync(af[i], &Es[cur][wm*32 + i*16][kk], 40);
            #pragma unroll
            for (int j = 0; j < 2; j++) wmma::load_matrix_sync(bf[j], &Vs[cur][kk][wn*32 + j*16], 72);
            #pragma unroll
            for (int i = 0; i < 2; i++)
                #pragma unroll
                for (int j = 0; j < 2; j++)
                    wmma::mma_sync(cf[i][j], af[i], bf[j], cf[i][j]);
        }
    }

    __syncthreads();   // all MMAs done; safe to reuse Es as staging
    if (t < 128) rsinv[t] = irs[(size_t)z * S_ + brow + t];
    __syncthreads();

    // epilogue: reuse Es as per-warp float stage, write fp16 (single rounding)
    float* stgw = (float*)&Es[0][0][0] + w * (16*20);
    int lane = t & 31;
    int r = lane >> 1, c = (lane & 1) * 8;
    #pragma unroll
    for (int i = 0; i < 2; i++)
        #pragma unroll
        for (int j = 0; j < 2; j++) {
            int rl = wm*32 + i*16;
            wmma::store_matrix_sync(stgw, cf[i][j], 20, wmma::mem_row_major);
            __syncwarp();
            float sc = rsinv[rl + r];
            __half hh[8];
            #pragma unroll
            for (int e = 0; e < 8; e++) hh[e] = __float2half_rn(stgw[r*20 + c + e] * sc);
            *(uint4*)(Cp + (brow + rl + r) * (size_t)E_ + wn*32 + j*16 + c) = *(uint4*)hh;
            __syncwarp();
        }
}

// ---------------- RoPE cos/sin table (double precision, one-time) ----------------
__global__ void build_rope_table(float* __restrict__ ct, float* __restrict__ st) {
    int idx = blockIdx.x * blockDim.x + threadIdx.x;
    if (idx >= S_ * 32) return;
    int i = idx & 31;
    int s = idx >> 5;
    double expo = ((double)(2*i)) / 64.0;
    double invf = pow(10000.0, -expo);
    double f = (double)s * invf;
    ct[idx] = (float)cos(f);
    st[idx] = (float)sin(f);
}

// -------- RoPE: fp32 in, fp16 out; bias folded, Q pre-scaled by 1/8 --------
__global__ void rope16(const float* __restrict__ Q, const float* __restrict__ K,
                       __half* __restrict__ Qo, __half* __restrict__ Ko,
                       const float* __restrict__ bq, const float* __restrict__ bk,
                       const float* __restrict__ ct, const float* __restrict__ st) {
    int id = blockIdx.x * blockDim.x + threadIdx.x;
    const int total = NTOK * H_ * 16;            // half2 pairs
    if (id >= 2 * total) return;
    bool isQ = (id < total);
    int r = isQ ? id : id - total;
    int i2   = r & 15;
    int h    = (r >> 4) & 15;
    int trow = r >> 8;
    int s    = trow & (S_ - 1);
    int ci   = s*32 + i2*2;
    float c0 = ct[ci], c1 = ct[ci+1];
    float s0 = st[ci], s1 = st[ci+1];
    const float* bias = isQ ? bq : bk;
    const float* X = isQ ? Q : K;
    __half* Xo = isQ ? Qo : Ko;
    float scl = isQ ? 0.125f : 1.0f;
    int bc = h*D_ + i2*2;
    size_t base = (size_t)trow * E_ + bc;
    float x1a = X[base]      + bias[bc];
    float x1b = X[base+1]    + bias[bc+1];
    float x2a = X[base+32]   + bias[bc+32];
    float x2b = X[base+33]   + bias[bc+33];
    *(__half2*)(Xo + base)      = __floats2half2_rn((x1a*c0 - x2a*s0)*scl, (x1b*c1 - x2b*s1)*scl);
    *(__half2*)(Xo + base + 32) = __floats2half2_rn((x2a*c0 + x1a*s0)*scl, (x2b*c1 + x1b*s1)*scl);
}

// ---------------- Vb = h(V + bv) (single rounding) ----------------
__global__ void vbias(const float* __restrict__ V, const float* __restrict__ bv,
                      __half* __restrict__ Vb) {
    size_t i = (size_t)blockIdx.x * blockDim.x + threadIdx.x;   // 8-elem group
    if (i >= (size_t)NTOK * E_ / 8) return;
    int col = (int)((i << 3) & (E_ - 1));
    const float4* vp = (const float4*)V + i*2;
    float4 a = vp[0], b = vp[1];
    const float4 b0 = *(const float4*)(bv + col);
    const float4 b1 = *(const float4*)(bv + col + 4);
    __half h[8];
    h[0]=__float2half_rn(a.x+b0.x); h[1]=__float2half_rn(a.y+b0.y);
    h[2]=__float2half_rn(a.z+b0.z); h[3]=__float2half_rn(a.w+b0.w);
    h[4]=__float2half_rn(b.x+b1.x); h[5]=__float2half_rn(b.y+b1.y);
    h[6]=__float2half_rn(b.z+b1.z); h[7]=__float2half_rn(b.w+b1.w);
    ((uint4*)Vb)[i] = *(uint4*)h;
}

// ---------------- attn_avg = mean over heads of E*irs ----------------
__global__ void avg_heads(const __half* __restrict__ Eg, const float* __restrict__ irs,
                          float* __restrict__ out) {
    size_t i = (size_t)blockIdx.x * blockDim.x + threadIdx.x;    // 8-elem group
    const size_t TOT = (size_t)B_ * S_ * (S_/8);
    if (i >= TOT) return;
    size_t k8 = i % (S_/8);
    size_t q  = (i / (S_/8)) % S_;
    size_t b  = i / ((size_t)(S_/8) * S_);
    float acc[8] = {0,0,0,0,0,0,0,0};
    #pragma unroll
    for (int h = 0; h < H_; h++) {
        size_t zh = b * H_ + h;
        uint4 raw = *(const uint4*)(Eg + (zh * S_ + q) * (size_t)S_ + k8*8);
        const __half* hp = (const __half*)&raw;
        float inv = irs[zh * S_ + q];
        #pragma unroll
        for (int e = 0; e < 8; e++)
            acc[e] += __half2float(hp[e]) * inv;
    }
    float* op = out + (b * S_ + q) * (size_t)S_ + k8*8;
    #pragma unroll
    for (int e = 0; e < 8; e++) op[e] = acc[e] * (1.0f/16.0f);
}

// ---------------- out += bo ----------------
__global__ void add_bias(float* __restrict__ out, const float* __restrict__ bo) {
    size_t i = (size_t)blockIdx.x * blockDim.x + threadIdx.x;
    if (i >= (size_t)NTOK * E_ / 4) return;
    int col = (int)((i << 2) & (E_ - 1));
    float4 v = ((float4*)out)[i];
    const float4 bb = *(const float4*)(bo + col);
    v.x += bb.x; v.y += bb.y; v.z += bb.z; v.w += bb.w;
    ((float4*)out)[i] = v;
}

// ---------------- launch ----------------
extern "C" void kernel_launch(void* const* d_in, const int* in_sizes, int n_in,
                              void* d_out, int out_size)
{
    const float* query = (const float*)d_in[0];
    const float* key   = (const float*)d_in[1];
    const float* value = (const float*)d_in[2];
    const float* Wq = (const float*)d_in[3];
    const float* bq = (const float*)d_in[4];
    const float* Wk = (const float*)d_in[5];
    const float* bk = (const float*)d_in[6];
    const float* Wv = (const float*)d_in[7];
    const float* bv = (const float*)d_in[8];
    const float* Wo = (const float*)d_in[9];
    const float* bo = (const float*)d_in[10];

    float* out      = (float*)d_out;
    float* attn_avg = out + (size_t)NTOK * E_;

    __half *qh,*kh,*vh,*Wqh,*Wkh,*Wvh,*Woh,*Qr,*Kr,*Vbp,*AOh,*Eh;
    float *Qp,*Kp,*Vp,*rs,*irs,*ctp,*stp;
    cudaGetSymbolAddress((void**)&qh,  d_qh);
    cudaGetSymbolAddress((void**)&kh,  d_kh);
    cudaGetSymbolAddress((void**)&vh,  d_vh);
    cudaGetSymbolAddress((void**)&Wqh, d_Wqh);
    cudaGetSymbolAddress((void**)&Wkh, d_Wkh);
    cudaGetSymbolAddress((void**)&Wvh, d_Wvh);
    cudaGetSymbolAddress((void**)&Woh, d_Woh);
    cudaGetSymbolAddress((void**)&Qp,  d_Q);
    cudaGetSymbolAddress((void**)&Kp,  d_K);
    cudaGetSymbolAddress((void**)&Vp,  d_V);
    cudaGetSymbolAddress((void**)&Qr,  d_Qr);
    cudaGetSymbolAddress((void**)&Kr,  d_Kr);
    cudaGetSymbolAddress((void**)&Vbp, d_Vb);
    cudaGetSymbolAddress((void**)&AOh, d_AOh);
    cudaGetSymbolAddress((void**)&Eh,  d_E);
    cudaGetSymbolAddress((void**)&rs,  d_rs);
    cudaGetSymbolAddress((void**)&irs, d_irs);
    cudaGetSymbolAddress((void**)&ctp, d_ct);
    cudaGetSymbolAddress((void**)&stp, d_st);

    build_rope_table<<<(S_*32)/256, 256>>>(ctp, stp);

    // zero rowsums
    const int NRS = B_*H_*S_;
    rs_zero<<<(NRS+255)/256, 256>>>(rs, NRS);

    // fp32 -> fp16 conversions (single rounding each; numerics unchanged)
    const int NTE8 = NTOK*E_/8, EE8 = E_*E_/8;
    cvt_h<<<(NTE8+255)/256, 256>>>(query, qh, NTE8);
    cvt_h<<<(NTE8+255)/256, 256>>>(key,   kh, NTE8);
    cvt_h<<<(NTE8+255)/256, 256>>>(value, vh, NTE8);
    cvt_h<<<(EE8+255)/256, 256>>>(Wq, Wqh, EE8);
    cvt_h<<<(EE8+255)/256, 256>>>(Wk, Wkh, EE8);
    cvt_h<<<(EE8+255)/256, 256>>>(Wv, Wvh, EE8);
    cvt_h<<<(EE8+255)/256, 256>>>(Wo, Woh, EE8);

    // QKV projections: fp16 in, fp32 out
    dim3 g1(E_/128, NTOK/128, 1);
    hgemm16<<<g1, 256>>>(qh, Wqh, Qp, E_, E_, E_, E_);
    hgemm16<<<g1, 256>>>(kh, Wkh, Kp, E_, E_, E_, E_);
    hgemm16<<<g1, 256>>>(vh, Wvh, Vp, E_, E_, E_, E_);

    // RoPE (+bias, +1/8 on Q): fp32 -> fp16
    rope16<<<(2 * NTOK * H_ * 16) / 256, 256>>>(Qp, Kp, Qr, Kr, bq, bk, ctp, stp);

    // Vb = h(V + bv)
    vbias<<<(NTOK*E_/8 + 255)/256, 256>>>(Vp, bv, Vbp);

    // E = exp(scores) fp16, rowsums accumulated atomically
    dim3 g3(S_/128, S_/128, B_*H_);
    hgemm_scores<<<g3, 256>>>(Qr, Kr, Eh, rs);

    // irs = 1/rs
    rs_inv<<<(NRS+255)/256, 256>>>(rs, irs, NRS);

    // AOh = h((E @ Vb) * irs), fp16
    dim3 g5(S_/128, 1, B_*H_);
    hgemm_pv<<<g5, 256>>>(Eh, Vbp, irs, AOh);

    // Output projection (fp16 in, fp32 out) + bias
    hgemm16<<<g1, 256>>>(AOh, Woh, out, E_, E_, E_, E_);
    add_bias<<<(NTOK*E_/4 + 255)/256, 256>>>(out, bo);

    // attn_avg from E + inverse row sums
    avg_heads<<<(B_*S_*(S_/8) + 255)/256, 256>>>(Eh, irs, attn_avg);
}